// round 13
// baseline (speedup 1.0000x reference)
#include <cuda_runtime.h>
#include <cuda_fp16.h>
#include <cstdint>

// ---------------- model constants ----------------
#define BSZ      512
#define NCH      129
#define NT       250
#define DINNER   256
#define DSTATE   16
#define NHEADS   4
#define CONVDIM  288
#define DPROJ    548
#define EPSV     1e-5f
#define ROWH     544        // gz(256)+xBC raw(288) fp16 per row

// GEMM tiling
#define TM     128
#define TN     144
#define TK     128
#define NJC    4
#define NKK    8
#define PITCHB 272
#define SPITCH 148

// scan prefetch ring
#define RD     8            // ring depth (lookahead 7)

// ---------------- device scratch ----------------
typedef unsigned long long ull;
__device__ float g_W[DPROJ * NCH];
__device__ float g_bias[DPROJ];
__device__ float g_v[DINNER];
__device__ __align__(16) __half g_zx[(size_t)BSZ * NT * ROWH];   // gz + raw xBC
__device__ __align__(16) float g_dtA[(size_t)BSZ * NT * 8];      // (dt,dA) x4 heads
__device__ __align__(16) __half g_cs[(size_t)BSZ * NT * 256];    // conv+silu x channels
__device__ __align__(16) ull g_bc[(size_t)BSZ * NT * 32];        // B,C pre-dup2 pairs
__device__ __align__(8)  float2 g_part[(size_t)BSZ * NT * NHEADS]; // (ss,p) per head
__device__ __align__(16) __half g_Wh[NJC * TN * TK];
__device__ float g_Wcol[576];
__device__ float g_biasP[576];

// ---------------- GEMM smem layout (bytes) ----------------
#define SM_AH    0
#define SM_BH    34816
#define SM_X128  75776
#define SM_W128  76288
#define SM_BIAS  76864
#define SMEM_SZ  77440

// ---------------- packed f32x2 helpers ----------------
__device__ __forceinline__ ull dup2(float v) {
    ull r; asm("mov.b64 %0, {%1, %1};" : "=l"(r) : "f"(v)); return r;
}
__device__ __forceinline__ ull pack2(float lo, float hi) {
    ull r; asm("mov.b64 %0, {%1, %2};" : "=l"(r) : "f"(lo), "f"(hi)); return r;
}
__device__ __forceinline__ ull ffma2(ull a, ull b, ull c) {
    ull d; asm("fma.rn.f32x2 %0, %1, %2, %3;" : "=l"(d) : "l"(a), "l"(b), "l"(c)); return d;
}
__device__ __forceinline__ ull fmul2(ull a, ull b) {
    ull d; asm("mul.rn.f32x2 %0, %1, %2;" : "=l"(d) : "l"(a), "l"(b)); return d;
}
__device__ __forceinline__ float2 unpk2(ull v) {
    float2 f; asm("mov.b64 {%0, %1}, %2;" : "=f"(f.x), "=f"(f.y) : "l"(v)); return f;
}

// ---------------- mma / ldmatrix / cp.async ----------------
__device__ __forceinline__ void mma16816(float* d, const uint32_t* a, const uint32_t* b) {
    asm volatile(
        "mma.sync.aligned.m16n8k16.row.col.f32.f16.f16.f32 "
        "{%0,%1,%2,%3}, {%4,%5,%6,%7}, {%8,%9}, {%0,%1,%2,%3};"
        : "+f"(d[0]), "+f"(d[1]), "+f"(d[2]), "+f"(d[3])
        : "r"(a[0]), "r"(a[1]), "r"(a[2]), "r"(a[3]), "r"(b[0]), "r"(b[1]));
}
__device__ __forceinline__ void ldsm4(uint32_t* r, uint32_t addr) {
    asm volatile("ldmatrix.sync.aligned.m8n8.x4.shared.b16 {%0,%1,%2,%3}, [%4];"
        : "=r"(r[0]), "=r"(r[1]), "=r"(r[2]), "=r"(r[3]) : "r"(addr));
}
__device__ __forceinline__ uint32_t smem_u32(const void* p) {
    uint32_t a;
    asm("{ .reg .u64 t; cvta.to.shared.u64 t, %1; cvt.u32.u64 %0, t; }" : "=r"(a) : "l"(p));
    return a;
}
#define CP_ASYNC4(sa, gp) asm volatile("cp.async.ca.shared.global [%0], [%1], 4;" :: "r"(sa), "l"(gp) : "memory")
#define CP_ASYNC8(sa, gp) asm volatile("cp.async.ca.shared.global [%0], [%1], 8;" :: "r"(sa), "l"(gp) : "memory")
#define CP_COMMIT()       asm volatile("cp.async.commit_group;" ::: "memory")
#define CP_WAIT6()        asm volatile("cp.async.wait_group 6;" ::: "memory")

// =====================================================================
// prep1: fused weights
// =====================================================================
__global__ void prep1_kernel(const float* __restrict__ in_proj_w,
                             const float* __restrict__ mixer_w,
                             const float* __restrict__ mixer_b,
                             const float* __restrict__ out_proj_w,
                             const float* __restrict__ head_w) {
    int idx = blockIdx.x * blockDim.x + threadIdx.x;
    const int NW = DPROJ * NCH;
    if (idx < NW) {
        int j = idx / NCH, c = idx - j * NCH;
        float a0 = 0.f, a1 = 0.f, a2 = 0.f, a3 = 0.f;
        #pragma unroll 8
        for (int d = 0; d < 128; d += 4) {
            a0 = fmaf(in_proj_w[j * 128 + d + 0], mixer_w[(d + 0) * NCH + c], a0);
            a1 = fmaf(in_proj_w[j * 128 + d + 1], mixer_w[(d + 1) * NCH + c], a1);
            a2 = fmaf(in_proj_w[j * 128 + d + 2], mixer_w[(d + 2) * NCH + c], a2);
            a3 = fmaf(in_proj_w[j * 128 + d + 3], mixer_w[(d + 3) * NCH + c], a3);
        }
        g_W[idx] = (a0 + a1) + (a2 + a3);
    } else if (idx < NW + DPROJ) {
        int j = idx - NW;
        float acc = 0.f;
        #pragma unroll 4
        for (int d = 0; d < 128; d++)
            acc = fmaf(in_proj_w[j * 128 + d], mixer_b[d], acc);
        g_bias[j] = acc;
    } else if (idx < NW + DPROJ + DINNER) {
        int i = idx - NW - DPROJ;
        float acc = 0.f;
        #pragma unroll 4
        for (int d = 0; d < 128; d++)
            acc = fmaf(out_proj_w[d * DINNER + i], head_w[d], acc);
        g_v[i] = acc;
    }
}

// =====================================================================
// prep2: W (k<128) -> fp16 chunk tiles [jc][n(144)][k(128)]
// =====================================================================
__global__ void prep2_kernel() {
    int idx = blockIdx.x * blockDim.x + threadIdx.x;
    const int NH = NJC * TN * TK;
    if (idx < NH) {
        int k = idx & 127;
        int t = idx >> 7;
        int n = t % TN;
        int jc = t / TN;
        int j = jc * TN + n;
        float val = (j < DPROJ) ? g_W[j * NCH + k] : 0.f;
        g_Wh[idx] = __float2half(val);
    } else if (idx < NH + 576) {
        int j = idx - NH;
        g_Wcol[j] = (j < DPROJ) ? g_W[j * NCH + 128] : 0.f;
    } else if (idx < NH + 1152) {
        int j = idx - NH - 576;
        g_biasP[j] = (j < DPROJ) ? g_bias[j] : 0.f;
    }
}

// =====================================================================
// gemm_mma: single-pass fp16 GEMM (unchanged from R12)
// =====================================================================
__global__ void __launch_bounds__(256, 2)
gemm_mma(const float* __restrict__ x,
         const float* __restrict__ dt_bias,
         const float* __restrict__ A_log) {
    extern __shared__ __align__(16) unsigned char sm[];
    const uint32_t sbase = smem_u32(sm);
    const int tid = threadIdx.x;
    const int wid = tid >> 5, lane = tid & 31;
    const int gid = lane >> 2, tig = lane & 3;
    const int tt = blockIdx.x, jc = blockIdx.y, b = blockIdx.z;
    const int t0 = tt * TM;

    {
        const unsigned char* src = (const unsigned char*)(g_Wh + (size_t)jc * (TN * TK));
        for (int i = tid; i < TN * 16; i += 256) {
            int n = i >> 4, q = i & 15;
            *(uint4*)(sm + SM_BH + n * PITCHB + q * 16) = *(const uint4*)(src + n * 256 + q * 16);
        }
    }
    {
        const float* xb = x + (size_t)b * (NCH * NT);
        for (int i = tid; i < 64 * TM; i += 256) {
            int cp = i >> 7, m = i & (TM - 1);
            int t = t0 + m;
            int c0 = 2 * cp;
            float v0 = (t < NT) ? xb[(size_t)c0 * NT + t] : 0.f;
            float v1 = (t < NT) ? xb[(size_t)(c0 + 1) * NT + t] : 0.f;
            uint32_t off = (uint32_t)m * PITCHB + (uint32_t)cp * 4;
            *(__half2*)(sm + SM_AH + off) = __half2{__float2half(v0), __float2half(v1)};
        }
    }
    if (tid < 128) {
        int t = t0 + tid;
        const float* xb = x + (size_t)b * (NCH * NT);
        *(float*)(sm + SM_X128 + tid * 4) = (t < NT) ? xb[(size_t)128 * NT + t] : 0.f;
    }
    for (int i = tid; i < TN; i += 256) {
        *(float*)(sm + SM_W128 + i * 4) = g_Wcol[jc * TN + i];
        *(float*)(sm + SM_BIAS + i * 4) = g_biasP[jc * TN + i];
    }
    __syncthreads();

    float acc[18][4];
    #pragma unroll
    for (int ni = 0; ni < 18; ni++)
        #pragma unroll
        for (int q = 0; q < 4; q++) acc[ni][q] = 0.f;

    const uint32_t aOff = (uint32_t)(wid * 16 + (lane & 15)) * PITCHB + (uint32_t)(lane >> 4) * 16;
    const uint32_t bOff = (uint32_t)(lane & 15) * PITCHB + (uint32_t)(lane >> 4) * 16;

    const uint32_t Ah = sbase + SM_AH + aOff;
    const uint32_t Bb = sbase + SM_BH + bOff;

    #pragma unroll
    for (int kk = 0; kk < NKK; kk++) {
        uint32_t ah[4];
        ldsm4(ah, Ah + kk * 32);
        #pragma unroll
        for (int q = 0; q < 9; q++) {
            uint32_t bb[4];
            ldsm4(bb, Bb + (uint32_t)(q * 16) * PITCHB + kk * 32);
            uint32_t f0[2] = { bb[0], bb[2] };
            uint32_t f1[2] = { bb[1], bb[3] };
            mma16816(acc[2 * q],     ah, f0);
            mma16816(acc[2 * q + 1], ah, f1);
        }
    }

    __syncthreads();
    float* stage = (float*)sm;
    {
        int r = wid * 16 + gid;
        #pragma unroll
        for (int ni = 0; ni < 18; ni++) {
            int c = ni * 8 + 2 * tig;
            *(float2*)(stage + r * SPITCH + c) = make_float2(acc[ni][0], acc[ni][1]);
            *(float2*)(stage + (r + 8) * SPITCH + c) = make_float2(acc[ni][2], acc[ni][3]);
        }
    }
    __syncthreads();

    const float* xs128 = (const float*)(sm + SM_X128);
    const float* sW = (const float*)(sm + SM_W128);
    const float* sBs = (const float*)(sm + SM_BIAS);
    for (int i = tid; i < TM * (TN / 4); i += 256) {
        int row = i / (TN / 4), q = i % (TN / 4);
        int t = t0 + row;
        int j = jc * TN + 4 * q;
        if (t >= NT) continue;
        const float* sp = stage + row * SPITCH + 4 * q;
        float xk = xs128[row];
        float o0 = fmaf(xk, sW[4 * q + 0], sp[0] + sBs[4 * q + 0]);
        float o1 = fmaf(xk, sW[4 * q + 1], sp[1] + sBs[4 * q + 1]);
        float o2 = fmaf(xk, sW[4 * q + 2], sp[2] + sBs[4 * q + 2]);
        float o3 = fmaf(xk, sW[4 * q + 3], sp[3] + sBs[4 * q + 3]);
        if (j + 3 < 256) {
            o0 = __fdividef(o0, 1.f + __expf(-o0));
            o1 = __fdividef(o1, 1.f + __expf(-o1));
            o2 = __fdividef(o2, 1.f + __expf(-o2));
            o3 = __fdividef(o3, 1.f + __expf(-o3));
            __half2 ha = __floats2half2_rn(o0, o1);
            __half2 hb = __floats2half2_rn(o2, o3);
            uint2 pk = { *(uint32_t*)&ha, *(uint32_t*)&hb };
            *(uint2*)(g_zx + ((size_t)b * NT + t) * ROWH + j) = pk;
        } else if (j + 3 < 544) {
            __half2 ha = __floats2half2_rn(o0, o1);
            __half2 hb = __floats2half2_rn(o2, o3);
            uint2 pk = { *(uint32_t*)&ha, *(uint32_t*)&hb };
            *(uint2*)(g_zx + ((size_t)b * NT + t) * ROWH + j) = pk;
        } else if (j == 544) {
            float ov[4] = { o0, o1, o2, o3 };
            float* dst = g_dtA + ((size_t)b * NT + t) * 8;
            float4 lo, hi;
            float r0 = ov[0] + dt_bias[0];
            float d0 = (r0 > 15.f) ? r0 : __logf(1.f + __expf(r0));
            lo.x = d0; lo.y = __expf(d0 * -__expf(A_log[0]));
            float r1 = ov[1] + dt_bias[1];
            float d1 = (r1 > 15.f) ? r1 : __logf(1.f + __expf(r1));
            lo.z = d1; lo.w = __expf(d1 * -__expf(A_log[1]));
            float r2 = ov[2] + dt_bias[2];
            float d2 = (r2 > 15.f) ? r2 : __logf(1.f + __expf(r2));
            hi.x = d2; hi.y = __expf(d2 * -__expf(A_log[2]));
            float r3 = ov[3] + dt_bias[3];
            float d3 = (r3 > 15.f) ? r3 : __logf(1.f + __expf(r3));
            hi.z = d3; hi.w = __expf(d3 * -__expf(A_log[3]));
            *(float4*)(dst) = lo;
            *(float4*)(dst + 4) = hi;
        }
    }
}

// =====================================================================
// conv_kernel: FULLY PARALLEL conv+silu over (b,t) — conv depends only
//   on raw inputs, not prior conv outputs. Writes cs fp16 (x channels)
//   and B/C as pre-duplicated f32x2 pairs.
//   grid (5 t-tiles, 512 b), 288 threads (= channel)
// =====================================================================
#define CTT 50
__global__ void __launch_bounds__(288)
conv_kernel(const float* __restrict__ conv_w, const float* __restrict__ conv_b) {
    const int tile = blockIdx.x, b = blockIdx.y;
    const int c = threadIdx.x;
    const int t0 = tile * CTT;

    const float w0 = conv_w[c * 4 + 0], w1 = conv_w[c * 4 + 1];
    const float w2 = conv_w[c * 4 + 2], w3 = conv_w[c * 4 + 3];
    const float cb = conv_b[c];

    const __half* src = g_zx + ((size_t)b * NT) * ROWH + 256 + c;
    __half* csout = g_cs + ((size_t)b * NT) * 256 + c;
    ull* bcout = g_bc + ((size_t)b * NT) * 32 + (c - 256);

    float h1 = (t0 - 1 >= 0) ? __half2float(src[(size_t)(t0 - 1) * ROWH]) : 0.f;
    float h2 = (t0 - 2 >= 0) ? __half2float(src[(size_t)(t0 - 2) * ROWH]) : 0.f;
    float h3 = (t0 - 3 >= 0) ? __half2float(src[(size_t)(t0 - 3) * ROWH]) : 0.f;

    #pragma unroll 2
    for (int tt = 0; tt < CTT; tt++) {
        int t = t0 + tt;
        float r = __half2float(src[(size_t)t * ROWH]);
        float cv = fmaf(w3, r, fmaf(w2, h1, fmaf(w1, h2, fmaf(w0, h3, cb))));
        h3 = h2; h2 = h1; h1 = r;
        float cs = __fdividef(cv, 1.f + __expf(-cv));
        if (c < 256) csout[(size_t)t * 256] = __float2half(cs);
        else         bcout[(size_t)t * 32] = dup2(cs);
    }
}

// =====================================================================
// scan: BARRIER-FREE. 128 threads = 4 independent warps (one per head).
//   All data per lane comes from its own cp.async slots or own-warp BC
//   ring (wait_group + __syncwarp). No __syncthreads in the loop.
//   Per step: state update + gate + shfl-reduce + lane0 partial store.
// =====================================================================
__global__ void __launch_bounds__(128, 4)
scan_kernel(const float* __restrict__ Dp, const float* __restrict__ norm_w) {
    const int b = blockIdx.x;
    const int tid = threadIdx.x;
    const int lane = tid & 31;
    const int h = tid >> 5;
    const int c0 = 2 * tid;

    __shared__ uint32_t sCS[RD][128];
    __shared__ uint32_t sGZ[RD][128];
    __shared__ __align__(8) float2 sDT[RD][128];
    __shared__ __align__(8) ull sBC[NHEADS][RD][32];

    const float nw0 = norm_w[c0] * g_v[c0];
    const float nw1 = norm_w[c0 + 1] * g_v[c0 + 1];
    const ull D2 = dup2(Dp[h]);

    ull s2[DSTATE];
    #pragma unroll
    for (int n = 0; n < DSTATE; n++) s2[n] = 0ULL;

    const __half* cs_g = g_cs + (size_t)b * NT * 256 + c0;
    const __half* gz_g = g_zx + (size_t)b * NT * ROWH + c0;
    const ull*    bc_g = g_bc + (size_t)b * NT * 32 + lane;
    const float*  dt_g = g_dtA + (size_t)b * NT * 8 + 2 * h;
    float2* part = g_part + ((size_t)b * NT) * NHEADS + h;

    const uint32_t aCS = smem_u32(&sCS[0][tid]);
    const uint32_t aGZ = smem_u32(&sGZ[0][tid]);
    const uint32_t aDT = smem_u32(&sDT[0][tid]);
    const uint32_t aBC = smem_u32(&sBC[h][0][lane]);

    // prologue: steps 0..6
    #pragma unroll
    for (int d = 0; d < RD - 1; d++) {
        CP_ASYNC4(aCS + d * 512, (const void*)(cs_g + (size_t)d * 256));
        CP_ASYNC4(aGZ + d * 512, (const void*)(gz_g + (size_t)d * ROWH));
        CP_ASYNC8(aDT + d * 1024, (const void*)(dt_g + (size_t)d * 8));
        CP_ASYNC8(aBC + d * 256, (const void*)(bc_g + (size_t)d * 32));
        CP_COMMIT();
    }

    for (int t = 0; t < NT; t++) {
        const int slot = t & (RD - 1);

        CP_WAIT6();
        __syncwarp();

        uint32_t csu = sCS[slot][tid];
        uint32_t gzu = sGZ[slot][tid];
        float2 dtA = sDT[slot][tid];
        float2 cs = __half22float2(*(const __half2*)&csu);
        float2 gz = __half22float2(*(const __half2*)&gzu);

        ull dA2 = dup2(dtA.y);
        ull dx2 = pack2(dtA.x * cs.x, dtA.x * cs.y);
        ull ya = fmul2(D2, pack2(cs.x, cs.y));
        ull yb = 0ULL;
        const ull* Bt = &sBC[h][slot][0];
        const ull* Ct = &sBC[h][slot][16];
        #pragma unroll
        for (int n = 0; n < DSTATE; n += 2) {
            s2[n]     = ffma2(s2[n],     dA2, fmul2(dx2, Bt[n]));
            ya        = ffma2(s2[n],     Ct[n], ya);
            s2[n + 1] = ffma2(s2[n + 1], dA2, fmul2(dx2, Bt[n + 1]));
            yb        = ffma2(s2[n + 1], Ct[n + 1], yb);
        }
        float2 yy = unpk2(ya);
        float2 yz = unpk2(yb);
        float g0 = (yy.x + yz.x) * gz.x;
        float g1 = (yy.y + yz.y) * gz.y;

        float ss = fmaf(g0, g0, g1 * g1);
        float p  = fmaf(g0, nw0, g1 * nw1);
        #pragma unroll
        for (int o = 16; o > 0; o >>= 1) {
            ss += __shfl_xor_sync(0xffffffffu, ss, o);
            p  += __shfl_xor_sync(0xffffffffu, p, o);
        }
        if (lane == 0) part[(size_t)t * NHEADS] = make_float2(ss, p);

        // issue step t+7
        {
            int s = t + RD - 1;
            if (s < NT) {
                int sl = s & (RD - 1);
                CP_ASYNC4(aCS + sl * 512, (const void*)(cs_g + (size_t)s * 256));
                CP_ASYNC4(aGZ + sl * 512, (const void*)(gz_g + (size_t)s * ROWH));
                CP_ASYNC8(aDT + sl * 1024, (const void*)(dt_g + (size_t)s * 8));
                CP_ASYNC8(aBC + sl * 256, (const void*)(bc_g + (size_t)s * 32));
            }
            CP_COMMIT();
        }
    }
}

// =====================================================================
// combine: per-b rsqrt + pool + head (tiny: reads 8KB per block)
// =====================================================================
__global__ void __launch_bounds__(256)
combine_kernel(const float* __restrict__ head_b, float* __restrict__ out) {
    const int b = blockIdx.x;
    const int tid = threadIdx.x;
    const int lane = tid & 31, wid = tid >> 5;
    __shared__ float sred[8];

    float val = 0.f;
    if (tid < NT) {
        const float2* pp = g_part + ((size_t)b * NT + tid) * NHEADS;
        float2 p0 = pp[0], p1 = pp[1], p2 = pp[2], p3 = pp[3];
        float SS = (p0.x + p1.x) + (p2.x + p3.x);
        float P  = (p0.y + p1.y) + (p2.y + p3.y);
        val = P * rsqrtf(SS * (1.f / 256.f) + EPSV);
    }
    #pragma unroll
    for (int o = 16; o > 0; o >>= 1) val += __shfl_xor_sync(0xffffffffu, val, o);
    if (lane == 0) sred[wid] = val;
    __syncthreads();
    if (tid == 0) {
        float tot = 0.f;
        #pragma unroll
        for (int w = 0; w < 8; w++) tot += sred[w];
        out[b] = tot * (1.f / (float)NT) + head_b[0];
    }
}

// =====================================================================
// launch
// =====================================================================
extern "C" void kernel_launch(void* const* d_in, const int* in_sizes, int n_in,
                              void* d_out, int out_size) {
    const float* x          = (const float*)d_in[0];
    const float* mixer_w    = (const float*)d_in[1];
    const float* mixer_b    = (const float*)d_in[2];
    const float* in_proj_w  = (const float*)d_in[3];
    const float* conv_w     = (const float*)d_in[4];
    const float* conv_b     = (const float*)d_in[5];
    const float* dt_bias    = (const float*)d_in[6];
    const float* A_log      = (const float*)d_in[7];
    const float* Dvec       = (const float*)d_in[8];
    const float* norm_w     = (const float*)d_in[9];
    const float* out_proj_w = (const float*)d_in[10];
    const float* head_w     = (const float*)d_in[11];
    const float* head_b     = (const float*)d_in[12];
    float* out = (float*)d_out;

    {
        int total = DPROJ * NCH + DPROJ + DINNER;
        prep1_kernel<<<(total + 255) / 256, 256>>>(in_proj_w, mixer_w, mixer_b,
                                                   out_proj_w, head_w);
    }
    {
        int total = NJC * TN * TK + 1152;
        prep2_kernel<<<(total + 255) / 256, 256>>>();
    }
    {
        cudaFuncSetAttribute(gemm_mma,
                             cudaFuncAttributeMaxDynamicSharedMemorySize, SMEM_SZ);
        dim3 grid(2, NJC, BSZ);
        gemm_mma<<<grid, 256, SMEM_SZ>>>(x, dt_bias, A_log);
    }
    {
        dim3 grid(NT / CTT, BSZ);   // (5, 512)
        conv_kernel<<<grid, CONVDIM>>>(conv_w, conv_b);
    }
    scan_kernel<<<BSZ, 128>>>(Dvec, norm_w);
    combine_kernel<<<BSZ, 256>>>(head_b, out);
}

// round 14
// speedup vs baseline: 1.1321x; 1.1321x over previous
#include <cuda_runtime.h>
#include <cuda_fp16.h>
#include <cstdint>

// ---------------- model constants ----------------
#define BSZ      512
#define NCH      129
#define NT       250
#define DINNER   256
#define DSTATE   16
#define NHEADS   4
#define CONVDIM  288
#define DPROJ    548
#define EPSV     1e-5f
#define ROWH     544        // gz(256)+xBC raw(288) fp16 per row

// GEMM tiling
#define TM     128
#define TN     144
#define TK     128
#define NJC    4
#define NKK    8
#define PITCHB 272
#define SPITCH 148

// scan prefetch ring
#define RD     8            // ring depth (lookahead 7)

// ---------------- device scratch ----------------
typedef unsigned long long ull;
__device__ float g_W[DPROJ * NCH];
__device__ float g_bias[DPROJ];
__device__ float g_v[DINNER];
__device__ __align__(16) __half g_xh[(size_t)BSZ * 256 * 128];   // x fp16 [b][t][k], 32 MB
__device__ __align__(16) __half g_zx[(size_t)BSZ * NT * ROWH];   // gz + raw xBC
__device__ __align__(16) float g_dtA[(size_t)BSZ * NT * 8];      // (dt,dA) x4 heads
__device__ __align__(16) __half g_gout[(size_t)BSZ * NT * 256];  // gated outputs
__device__ __align__(16) __half g_Wh[NJC * TN * TK];
__device__ float g_Wcol[576];
__device__ float g_biasP[576];

// ---------------- GEMM smem layout (bytes) ----------------
#define SM_AH    0
#define SM_BH    34816
#define SM_X128  75776
#define SM_W128  76288
#define SM_BIAS  76864
#define SMEM_SZ  77440

// ---------------- packed f32x2 helpers ----------------
__device__ __forceinline__ ull dup2(float v) {
    ull r; asm("mov.b64 %0, {%1, %1};" : "=l"(r) : "f"(v)); return r;
}
__device__ __forceinline__ ull pack2(float lo, float hi) {
    ull r; asm("mov.b64 %0, {%1, %2};" : "=l"(r) : "f"(lo), "f"(hi)); return r;
}
__device__ __forceinline__ ull ffma2(ull a, ull b, ull c) {
    ull d; asm("fma.rn.f32x2 %0, %1, %2, %3;" : "=l"(d) : "l"(a), "l"(b), "l"(c)); return d;
}
__device__ __forceinline__ ull fmul2(ull a, ull b) {
    ull d; asm("mul.rn.f32x2 %0, %1, %2;" : "=l"(d) : "l"(a), "l"(b)); return d;
}
__device__ __forceinline__ float2 unpk2(ull v) {
    float2 f; asm("mov.b64 {%0, %1}, %2;" : "=f"(f.x), "=f"(f.y) : "l"(v)); return f;
}

// ---------------- mma / ldmatrix / cp.async ----------------
__device__ __forceinline__ void mma16816(float* d, const uint32_t* a, const uint32_t* b) {
    asm volatile(
        "mma.sync.aligned.m16n8k16.row.col.f32.f16.f16.f32 "
        "{%0,%1,%2,%3}, {%4,%5,%6,%7}, {%8,%9}, {%0,%1,%2,%3};"
        : "+f"(d[0]), "+f"(d[1]), "+f"(d[2]), "+f"(d[3])
        : "r"(a[0]), "r"(a[1]), "r"(a[2]), "r"(a[3]), "r"(b[0]), "r"(b[1]));
}
__device__ __forceinline__ void ldsm4(uint32_t* r, uint32_t addr) {
    asm volatile("ldmatrix.sync.aligned.m8n8.x4.shared.b16 {%0,%1,%2,%3}, [%4];"
        : "=r"(r[0]), "=r"(r[1]), "=r"(r[2]), "=r"(r[3]) : "r"(addr));
}
__device__ __forceinline__ uint32_t smem_u32(const void* p) {
    uint32_t a;
    asm("{ .reg .u64 t; cvta.to.shared.u64 t, %1; cvt.u32.u64 %0, t; }" : "=r"(a) : "l"(p));
    return a;
}
#define CP_ASYNC4(sa, gp) asm volatile("cp.async.ca.shared.global [%0], [%1], 4;" :: "r"(sa), "l"(gp) : "memory")
#define CP_ASYNC8(sa, gp) asm volatile("cp.async.ca.shared.global [%0], [%1], 8;" :: "r"(sa), "l"(gp) : "memory")
#define CP_COMMIT()       asm volatile("cp.async.commit_group;" ::: "memory")
#define CP_WAIT6()        asm volatile("cp.async.wait_group 6;" ::: "memory")

// =====================================================================
// prep1: fused weights
// =====================================================================
__global__ void prep1_kernel(const float* __restrict__ in_proj_w,
                             const float* __restrict__ mixer_w,
                             const float* __restrict__ mixer_b,
                             const float* __restrict__ out_proj_w,
                             const float* __restrict__ head_w) {
    int idx = blockIdx.x * blockDim.x + threadIdx.x;
    const int NW = DPROJ * NCH;
    if (idx < NW) {
        int j = idx / NCH, c = idx - j * NCH;
        float a0 = 0.f, a1 = 0.f, a2 = 0.f, a3 = 0.f;
        #pragma unroll 8
        for (int d = 0; d < 128; d += 4) {
            a0 = fmaf(in_proj_w[j * 128 + d + 0], mixer_w[(d + 0) * NCH + c], a0);
            a1 = fmaf(in_proj_w[j * 128 + d + 1], mixer_w[(d + 1) * NCH + c], a1);
            a2 = fmaf(in_proj_w[j * 128 + d + 2], mixer_w[(d + 2) * NCH + c], a2);
            a3 = fmaf(in_proj_w[j * 128 + d + 3], mixer_w[(d + 3) * NCH + c], a3);
        }
        g_W[idx] = (a0 + a1) + (a2 + a3);
    } else if (idx < NW + DPROJ) {
        int j = idx - NW;
        float acc = 0.f;
        #pragma unroll 4
        for (int d = 0; d < 128; d++)
            acc = fmaf(in_proj_w[j * 128 + d], mixer_b[d], acc);
        g_bias[j] = acc;
    } else if (idx < NW + DPROJ + DINNER) {
        int i = idx - NW - DPROJ;
        float acc = 0.f;
        #pragma unroll 4
        for (int d = 0; d < 128; d++)
            acc = fmaf(out_proj_w[d * DINNER + i], head_w[d], acc);
        g_v[i] = acc;
    }
}

// =====================================================================
// prep2: W (k<128) -> fp16 chunk tiles [jc][n(144)][k(128)]
// =====================================================================
__global__ void prep2_kernel() {
    int idx = blockIdx.x * blockDim.x + threadIdx.x;
    const int NH = NJC * TN * TK;
    if (idx < NH) {
        int k = idx & 127;
        int t = idx >> 7;
        int n = t % TN;
        int jc = t / TN;
        int j = jc * TN + n;
        float val = (j < DPROJ) ? g_W[j * NCH + k] : 0.f;
        g_Wh[idx] = __float2half(val);
    } else if (idx < NH + 576) {
        int j = idx - NH;
        g_Wcol[j] = (j < DPROJ) ? g_W[j * NCH + 128] : 0.f;
    } else if (idx < NH + 1152) {
        int j = idx - NH - 576;
        g_biasP[j] = (j < DPROJ) ? g_bias[j] : 0.f;
    }
}

// =====================================================================
// xh_kernel: transpose+convert x (fp32 [b][c][t]) -> g_xh (fp16 [b][t][k])
//   smem fp32 tile 128x65 (conflict-free both phases). t>=NT zero-padded.
// =====================================================================
__global__ void __launch_bounds__(256)
xh_kernel(const float* __restrict__ x) {
    __shared__ float tile[128][65];
    const int tt0 = blockIdx.x * 64, b = blockIdx.y;
    const float* xb = x + (size_t)b * (NCH * NT);

    for (int i = threadIdx.x; i < 128 * 64; i += 256) {
        int c = i >> 6, t = i & 63;
        int gt = tt0 + t;
        tile[c][t] = (gt < NT) ? xb[(size_t)c * NT + gt] : 0.f;
    }
    __syncthreads();
    __half* dst = g_xh + ((size_t)b * 256 + tt0) * 128;
    for (int i = threadIdx.x; i < 64 * 64; i += 256) {
        int t = i >> 6, cp = i & 63;
        __half2 h = __floats2half2_rn(tile[2 * cp][t], tile[2 * cp + 1][t]);
        *(__half2*)(dst + (size_t)t * 128 + 2 * cp) = h;
    }
}

// =====================================================================
// gemm_mma: single-pass fp16 GEMM; A tile now pure 16B copies from g_xh
// =====================================================================
__global__ void __launch_bounds__(256, 2)
gemm_mma(const float* __restrict__ x,
         const float* __restrict__ dt_bias,
         const float* __restrict__ A_log) {
    extern __shared__ __align__(16) unsigned char sm[];
    const uint32_t sbase = smem_u32(sm);
    const int tid = threadIdx.x;
    const int wid = tid >> 5, lane = tid & 31;
    const int gid = lane >> 2, tig = lane & 3;
    const int tt = blockIdx.x, jc = blockIdx.y, b = blockIdx.z;
    const int t0 = tt * TM;

    // ---- B tile: 16B copies
    {
        const unsigned char* src = (const unsigned char*)(g_Wh + (size_t)jc * (TN * TK));
        for (int i = tid; i < TN * 16; i += 256) {
            int n = i >> 4, q = i & 15;
            *(uint4*)(sm + SM_BH + n * PITCHB + q * 16) = *(const uint4*)(src + n * 256 + q * 16);
        }
    }
    // ---- A tile: 16B copies from pre-converted g_xh
    {
        const uint4* src = (const uint4*)(g_xh + ((size_t)b * 256 + t0) * 128);
        for (int i = tid; i < TM * 16; i += 256) {
            int m = i >> 4, q = i & 15;
            *(uint4*)(sm + SM_AH + m * PITCHB + q * 16) = src[m * 16 + q];
        }
    }
    // ---- epilogue constants
    if (tid < 128) {
        int t = t0 + tid;
        const float* xb = x + (size_t)b * (NCH * NT);
        *(float*)(sm + SM_X128 + tid * 4) = (t < NT) ? xb[(size_t)128 * NT + t] : 0.f;
    }
    for (int i = tid; i < TN; i += 256) {
        *(float*)(sm + SM_W128 + i * 4) = g_Wcol[jc * TN + i];
        *(float*)(sm + SM_BIAS + i * 4) = g_biasP[jc * TN + i];
    }
    __syncthreads();

    float acc[18][4];
    #pragma unroll
    for (int ni = 0; ni < 18; ni++)
        #pragma unroll
        for (int q = 0; q < 4; q++) acc[ni][q] = 0.f;

    const uint32_t aOff = (uint32_t)(wid * 16 + (lane & 15)) * PITCHB + (uint32_t)(lane >> 4) * 16;
    const uint32_t bOff = (uint32_t)(lane & 15) * PITCHB + (uint32_t)(lane >> 4) * 16;

    const uint32_t Ah = sbase + SM_AH + aOff;
    const uint32_t Bb = sbase + SM_BH + bOff;

    #pragma unroll
    for (int kk = 0; kk < NKK; kk++) {
        uint32_t ah[4];
        ldsm4(ah, Ah + kk * 32);
        #pragma unroll
        for (int q = 0; q < 9; q++) {
            uint32_t bb[4];
            ldsm4(bb, Bb + (uint32_t)(q * 16) * PITCHB + kk * 32);
            uint32_t f0[2] = { bb[0], bb[2] };
            uint32_t f1[2] = { bb[1], bb[3] };
            mma16816(acc[2 * q],     ah, f0);
            mma16816(acc[2 * q + 1], ah, f1);
        }
    }

    __syncthreads();
    float* stage = (float*)sm;
    {
        int r = wid * 16 + gid;
        #pragma unroll
        for (int ni = 0; ni < 18; ni++) {
            int c = ni * 8 + 2 * tig;
            *(float2*)(stage + r * SPITCH + c) = make_float2(acc[ni][0], acc[ni][1]);
            *(float2*)(stage + (r + 8) * SPITCH + c) = make_float2(acc[ni][2], acc[ni][3]);
        }
    }
    __syncthreads();

    const float* xs128 = (const float*)(sm + SM_X128);
    const float* sW = (const float*)(sm + SM_W128);
    const float* sBs = (const float*)(sm + SM_BIAS);
    for (int i = tid; i < TM * (TN / 4); i += 256) {
        int row = i / (TN / 4), q = i % (TN / 4);
        int t = t0 + row;
        int j = jc * TN + 4 * q;
        if (t >= NT) continue;
        const float* sp = stage + row * SPITCH + 4 * q;
        float xk = xs128[row];
        float o0 = fmaf(xk, sW[4 * q + 0], sp[0] + sBs[4 * q + 0]);
        float o1 = fmaf(xk, sW[4 * q + 1], sp[1] + sBs[4 * q + 1]);
        float o2 = fmaf(xk, sW[4 * q + 2], sp[2] + sBs[4 * q + 2]);
        float o3 = fmaf(xk, sW[4 * q + 3], sp[3] + sBs[4 * q + 3]);
        if (j + 3 < 256) {
            o0 = __fdividef(o0, 1.f + __expf(-o0));
            o1 = __fdividef(o1, 1.f + __expf(-o1));
            o2 = __fdividef(o2, 1.f + __expf(-o2));
            o3 = __fdividef(o3, 1.f + __expf(-o3));
            __half2 ha = __floats2half2_rn(o0, o1);
            __half2 hb = __floats2half2_rn(o2, o3);
            uint2 pk = { *(uint32_t*)&ha, *(uint32_t*)&hb };
            *(uint2*)(g_zx + ((size_t)b * NT + t) * ROWH + j) = pk;
        } else if (j + 3 < 544) {
            __half2 ha = __floats2half2_rn(o0, o1);
            __half2 hb = __floats2half2_rn(o2, o3);
            uint2 pk = { *(uint32_t*)&ha, *(uint32_t*)&hb };
            *(uint2*)(g_zx + ((size_t)b * NT + t) * ROWH + j) = pk;
        } else if (j == 544) {
            float ov[4] = { o0, o1, o2, o3 };
            float* dst = g_dtA + ((size_t)b * NT + t) * 8;
            float4 lo, hi;
            float r0 = ov[0] + dt_bias[0];
            float d0 = (r0 > 15.f) ? r0 : __logf(1.f + __expf(r0));
            lo.x = d0; lo.y = __expf(d0 * -__expf(A_log[0]));
            float r1 = ov[1] + dt_bias[1];
            float d1 = (r1 > 15.f) ? r1 : __logf(1.f + __expf(r1));
            lo.z = d1; lo.w = __expf(d1 * -__expf(A_log[1]));
            float r2 = ov[2] + dt_bias[2];
            float d2 = (r2 > 15.f) ? r2 : __logf(1.f + __expf(r2));
            hi.x = d2; hi.y = __expf(d2 * -__expf(A_log[2]));
            float r3 = ov[3] + dt_bias[3];
            float d3 = (r3 > 15.f) ? r3 : __logf(1.f + __expf(r3));
            hi.z = d3; hi.w = __expf(d3 * -__expf(A_log[3]));
            *(float4*)(dst) = lo;
            *(float4*)(dst + 4) = hi;
        }
    }
}

// =====================================================================
// scan: R12 version (measured 171us) — 160 threads, conv inside,
//   cp.async ring depth 8, 1 barrier/step, fire-and-forget g store
// =====================================================================
__global__ void __launch_bounds__(160, 4)
scan_kernel(const float* __restrict__ conv_w, const float* __restrict__ conv_b,
            const float* __restrict__ Dp) {
    const int b = blockIdx.x;
    const int tid = threadIdx.x;
    const int c0 = 2 * tid;
    const int h = tid >> 5;

    __shared__ uint32_t sXBC[RD][144];
    __shared__ uint32_t sGZ[RD][128];
    __shared__ float    sDTA[RD][8];
    __shared__ __align__(8) float2 sB2[2][DSTATE];
    __shared__ __align__(8) float2 sC2[2][DSTATE];

    const bool isConv = (tid < 144);
    const bool isScan = (tid < 128);
    const bool isDt   = (tid >= 144 && tid < 148);

    ull wk0 = 0, wk1 = 0, wk2_ = 0, wk3 = 0, cb2 = 0;
    if (isConv) {
        wk0 = pack2(conv_w[c0 * 4 + 0], conv_w[(c0 + 1) * 4 + 0]);
        wk1 = pack2(conv_w[c0 * 4 + 1], conv_w[(c0 + 1) * 4 + 1]);
        wk2_ = pack2(conv_w[c0 * 4 + 2], conv_w[(c0 + 1) * 4 + 2]);
        wk3 = pack2(conv_w[c0 * 4 + 3], conv_w[(c0 + 1) * 4 + 3]);
        cb2 = pack2(conv_b[c0], conv_b[c0 + 1]);
    }
    ull h1 = 0ULL, h2 = 0ULL, h3 = 0ULL;

    ull D2 = 0ULL;
    if (isScan) D2 = dup2(Dp[h]);

    ull s2[DSTATE];
    #pragma unroll
    for (int n = 0; n < DSTATE; n++) s2[n] = 0ULL;

    const __half* zx = g_zx + (size_t)b * NT * ROWH;
    const float* dtp = g_dtA + (size_t)b * NT * 8;
    __half* gout = g_gout + (size_t)b * NT * 256;

    uint32_t aXBC = isConv ? smem_u32(&sXBC[0][tid]) : 0;
    uint32_t aGZ  = isScan ? smem_u32(&sGZ[0][tid]) : 0;
    uint32_t aDTA = isDt   ? smem_u32(&sDTA[0][2 * (tid - 144)]) : 0;

    #pragma unroll
    for (int d = 0; d < RD - 1; d++) {
        if (isConv) CP_ASYNC4(aXBC + d * 144 * 4, (const void*)(zx + (size_t)d * ROWH + 256 + c0));
        if (isScan) CP_ASYNC4(aGZ + d * 128 * 4, (const void*)(zx + (size_t)d * ROWH + c0));
        if (isDt)   CP_ASYNC8(aDTA + d * 8 * 4, (const void*)(dtp + (size_t)d * 8 + 2 * (tid - 144)));
        CP_COMMIT();
    }

    for (int t = 0; t < NT; t++) {
        const int slot = t & (RD - 1);
        const int buf = t & 1;

        CP_WAIT6();

        float cs0 = 0.f, cs1 = 0.f;
        if (isConv) {
            uint32_t rawu = sXBC[slot][tid];
            float2 fr = __half22float2(*(const __half2*)&rawu);
            ull r2 = pack2(fr.x, fr.y);
            ull cv2 = ffma2(wk3, r2, ffma2(wk2_, h1, ffma2(wk1, h2, ffma2(wk0, h3, cb2))));
            h3 = h2; h2 = h1; h1 = r2;
            float2 cv = unpk2(cv2);
            cs0 = __fdividef(cv.x, 1.f + __expf(-cv.x));
            cs1 = __fdividef(cv.y, 1.f + __expf(-cv.y));
            if (tid >= 128) {
                if (tid < 136) {
                    int k = 2 * (tid - 128);
                    sB2[buf][k]     = make_float2(cs0, cs0);
                    sB2[buf][k + 1] = make_float2(cs1, cs1);
                } else {
                    int k = 2 * (tid - 136);
                    sC2[buf][k]     = make_float2(cs0, cs0);
                    sC2[buf][k + 1] = make_float2(cs1, cs1);
                }
            }
        }
        __syncthreads();

        if (isScan) {
            float2 dtA = *(const float2*)&sDTA[slot][2 * h];
            uint32_t gzu = sGZ[slot][tid];
            float2 gz = __half22float2(*(const __half2*)&gzu);
            ull dA2 = dup2(dtA.y);
            ull dx2 = pack2(dtA.x * cs0, dtA.x * cs1);
            ull ya = fmul2(D2, pack2(cs0, cs1));
            ull yb = 0ULL;
            #pragma unroll
            for (int n = 0; n < DSTATE; n += 2) {
                s2[n]     = ffma2(s2[n],     dA2, fmul2(dx2, *(const ull*)&sB2[buf][n]));
                ya        = ffma2(s2[n],     *(const ull*)&sC2[buf][n], ya);
                s2[n + 1] = ffma2(s2[n + 1], dA2, fmul2(dx2, *(const ull*)&sB2[buf][n + 1]));
                yb        = ffma2(s2[n + 1], *(const ull*)&sC2[buf][n + 1], yb);
            }
            float2 yy = unpk2(ya);
            float2 yz = unpk2(yb);
            float g0 = (yy.x + yz.x) * gz.x;
            float g1 = (yy.y + yz.y) * gz.y;
            __half2 gh = __floats2half2_rn(g0, g1);
            *(__half2*)(gout + (size_t)t * 256 + c0) = gh;
        }

        {
            int s = t + RD - 1;
            if (s < NT) {
                int sl = s & (RD - 1);
                if (isConv) CP_ASYNC4(aXBC + sl * 144 * 4, (const void*)(zx + (size_t)s * ROWH + 256 + c0));
                if (isScan) CP_ASYNC4(aGZ + sl * 128 * 4, (const void*)(zx + (size_t)s * ROWH + c0));
                if (isDt)   CP_ASYNC8(aDTA + sl * 8 * 4, (const void*)(dtp + (size_t)s * 8 + 2 * (tid - 144)));
            }
            CP_COMMIT();
        }
    }
}

// =====================================================================
// combine: fully parallel RMS sums + rsqrt + pool + head
// =====================================================================
__global__ void __launch_bounds__(256)
combine_kernel(const float* __restrict__ norm_w,
               const float* __restrict__ head_b, float* __restrict__ out) {
    const int b = blockIdx.x;
    const int tid = threadIdx.x;
    const int lane = tid & 31, wid = tid >> 5;

    __shared__ float s_nwv[256];
    __shared__ float sred[8];

    s_nwv[tid] = norm_w[tid] * g_v[tid];
    __syncthreads();

    const __half* gp = g_gout + (size_t)b * NT * 256;
    float facc = 0.f;

    for (int t = wid; t < NT; t += 8) {
        const uint2* rowp = (const uint2*)(gp + (size_t)t * 256);
        uint2 u0 = rowp[2 * lane];
        uint2 u1 = rowp[2 * lane + 1];
        const float* nv = s_nwv + 8 * lane;
        float2 a = __half22float2(*(__half2*)&u0.x);
        float2 c = __half22float2(*(__half2*)&u0.y);
        float2 d = __half22float2(*(__half2*)&u1.x);
        float2 e = __half22float2(*(__half2*)&u1.y);
        float SS = a.x * a.x + a.y * a.y + c.x * c.x + c.y * c.y
                 + d.x * d.x + d.y * d.y + e.x * e.x + e.y * e.y;
        float P = a.x * nv[0] + a.y * nv[1] + c.x * nv[2] + c.y * nv[3]
                + d.x * nv[4] + d.y * nv[5] + e.x * nv[6] + e.y * nv[7];
        #pragma unroll
        for (int o = 16; o > 0; o >>= 1) {
            SS += __shfl_xor_sync(0xffffffffu, SS, o);
            P  += __shfl_xor_sync(0xffffffffu, P, o);
        }
        if (lane == 0)
            facc = fmaf(P, rsqrtf(SS * (1.f / 256.f) + EPSV), facc);
    }

    if (lane == 0) sred[wid] = facc;
    __syncthreads();
    if (tid == 0) {
        float tot = 0.f;
        #pragma unroll
        for (int w = 0; w < 8; w++) tot += sred[w];
        out[b] = tot * (1.f / (float)NT) + head_b[0];
    }
}

// =====================================================================
// launch
// =====================================================================
extern "C" void kernel_launch(void* const* d_in, const int* in_sizes, int n_in,
                              void* d_out, int out_size) {
    const float* x          = (const float*)d_in[0];
    const float* mixer_w    = (const float*)d_in[1];
    const float* mixer_b    = (const float*)d_in[2];
    const float* in_proj_w  = (const float*)d_in[3];
    const float* conv_w     = (const float*)d_in[4];
    const float* conv_b     = (const float*)d_in[5];
    const float* dt_bias    = (const float*)d_in[6];
    const float* A_log      = (const float*)d_in[7];
    const float* Dvec       = (const float*)d_in[8];
    const float* norm_w     = (const float*)d_in[9];
    const float* out_proj_w = (const float*)d_in[10];
    const float* head_w     = (const float*)d_in[11];
    const float* head_b     = (const float*)d_in[12];
    float* out = (float*)d_out;

    {
        int total = DPROJ * NCH + DPROJ + DINNER;
        prep1_kernel<<<(total + 255) / 256, 256>>>(in_proj_w, mixer_w, mixer_b,
                                                   out_proj_w, head_w);
    }
    {
        int total = NJC * TN * TK + 1152;
        prep2_kernel<<<(total + 255) / 256, 256>>>();
    }
    {
        dim3 grid(4, BSZ);
        xh_kernel<<<grid, 256>>>(x);
    }
    {
        cudaFuncSetAttribute(gemm_mma,
                             cudaFuncAttributeMaxDynamicSharedMemorySize, SMEM_SZ);
        dim3 grid(2, NJC, BSZ);
        gemm_mma<<<grid, 256, SMEM_SZ>>>(x, dt_bias, A_log);
    }
    scan_kernel<<<BSZ, 160>>>(conv_w, conv_b, Dvec);
    combine_kernel<<<BSZ, 256>>>(norm_w, head_b, out);
}

// round 15
// speedup vs baseline: 1.2746x; 1.1260x over previous
#include <cuda_runtime.h>
#include <cuda_fp16.h>
#include <cstdint>

// ---------------- model constants ----------------
#define BSZ      512
#define NCH      129
#define NT       250
#define DINNER   256
#define DSTATE   16
#define NHEADS   4
#define CONVDIM  288
#define DPROJ    548
#define EPSV     1e-5f
#define ROWH     544        // gz(256)+xBC raw(288) fp16 per row

// GEMM tiling
#define TM     128
#define TN     144
#define TK     128
#define NJC    4
#define NKK    8
#define PITCHB 272
#define SPITCH 148

// scan prefetch ring
#define RD     8

// ---------------- device scratch ----------------
typedef unsigned long long ull;
__device__ float g_W[DPROJ * NCH];
__device__ float g_bias[DPROJ];
__device__ float g_v[DINNER];
__device__ __align__(16) __half g_xh[(size_t)BSZ * 256 * 128];   // x fp16 [b][t][k]
__device__ __align__(16) __half g_zx[(size_t)BSZ * NT * ROWH];
__device__ __align__(16) float g_dtA[(size_t)BSZ * NT * 8];
__device__ __align__(16) __half g_gout[(size_t)BSZ * NT * 256];
__device__ __align__(16) __half g_Wh[NJC * TN * TK];
__device__ float g_Wcol[576];
__device__ float g_biasP[576];

// ---------------- GEMM smem layout (bytes) ----------------
#define SM_AH    0
#define SM_BH    34816
#define SM_X128  75776
#define SM_W128  76288
#define SM_BIAS  76864
#define SMEM_SZ  77440

// ---------------- packed f32x2 helpers ----------------
__device__ __forceinline__ ull dup2(float v) {
    ull r; asm("mov.b64 %0, {%1, %1};" : "=l"(r) : "f"(v)); return r;
}
__device__ __forceinline__ ull pack2(float lo, float hi) {
    ull r; asm("mov.b64 %0, {%1, %2};" : "=l"(r) : "f"(lo), "f"(hi)); return r;
}
__device__ __forceinline__ ull ffma2(ull a, ull b, ull c) {
    ull d; asm("fma.rn.f32x2 %0, %1, %2, %3;" : "=l"(d) : "l"(a), "l"(b), "l"(c)); return d;
}
__device__ __forceinline__ ull fmul2(ull a, ull b) {
    ull d; asm("mul.rn.f32x2 %0, %1, %2;" : "=l"(d) : "l"(a), "l"(b)); return d;
}
__device__ __forceinline__ float2 unpk2(ull v) {
    float2 f; asm("mov.b64 {%0, %1}, %2;" : "=f"(f.x), "=f"(f.y) : "l"(v)); return f;
}

// ---------------- mma / ldmatrix / cp.async ----------------
__device__ __forceinline__ void mma16816(float* d, const uint32_t* a, const uint32_t* b) {
    asm volatile(
        "mma.sync.aligned.m16n8k16.row.col.f32.f16.f16.f32 "
        "{%0,%1,%2,%3}, {%4,%5,%6,%7}, {%8,%9}, {%0,%1,%2,%3};"
        : "+f"(d[0]), "+f"(d[1]), "+f"(d[2]), "+f"(d[3])
        : "r"(a[0]), "r"(a[1]), "r"(a[2]), "r"(a[3]), "r"(b[0]), "r"(b[1]));
}
__device__ __forceinline__ void ldsm4(uint32_t* r, uint32_t addr) {
    asm volatile("ldmatrix.sync.aligned.m8n8.x4.shared.b16 {%0,%1,%2,%3}, [%4];"
        : "=r"(r[0]), "=r"(r[1]), "=r"(r[2]), "=r"(r[3]) : "r"(addr));
}
__device__ __forceinline__ void ldsm2(uint32_t* r, uint32_t addr) {
    asm volatile("ldmatrix.sync.aligned.m8n8.x2.shared.b16 {%0,%1}, [%2];"
        : "=r"(r[0]), "=r"(r[1]) : "r"(addr));
}
__device__ __forceinline__ uint32_t smem_u32(const void* p) {
    uint32_t a;
    asm("{ .reg .u64 t; cvta.to.shared.u64 t, %1; cvt.u32.u64 %0, t; }" : "=r"(a) : "l"(p));
    return a;
}
#define CP_ASYNC4(sa, gp) asm volatile("cp.async.ca.shared.global [%0], [%1], 4;" :: "r"(sa), "l"(gp) : "memory")
#define CP_ASYNC8(sa, gp) asm volatile("cp.async.ca.shared.global [%0], [%1], 8;" :: "r"(sa), "l"(gp) : "memory")
#define CP_COMMIT()       asm volatile("cp.async.commit_group;" ::: "memory")
#define CP_WAIT6()        asm volatile("cp.async.wait_group 6;" ::: "memory")

// =====================================================================
// prep1: fused weights
// =====================================================================
__global__ void prep1_kernel(const float* __restrict__ in_proj_w,
                             const float* __restrict__ mixer_w,
                             const float* __restrict__ mixer_b,
                             const float* __restrict__ out_proj_w,
                             const float* __restrict__ head_w) {
    int idx = blockIdx.x * blockDim.x + threadIdx.x;
    const int NW = DPROJ * NCH;
    if (idx < NW) {
        int j = idx / NCH, c = idx - j * NCH;
        float a0 = 0.f, a1 = 0.f, a2 = 0.f, a3 = 0.f;
        #pragma unroll 8
        for (int d = 0; d < 128; d += 4) {
            a0 = fmaf(in_proj_w[j * 128 + d + 0], mixer_w[(d + 0) * NCH + c], a0);
            a1 = fmaf(in_proj_w[j * 128 + d + 1], mixer_w[(d + 1) * NCH + c], a1);
            a2 = fmaf(in_proj_w[j * 128 + d + 2], mixer_w[(d + 2) * NCH + c], a2);
            a3 = fmaf(in_proj_w[j * 128 + d + 3], mixer_w[(d + 3) * NCH + c], a3);
        }
        g_W[idx] = (a0 + a1) + (a2 + a3);
    } else if (idx < NW + DPROJ) {
        int j = idx - NW;
        float acc = 0.f;
        #pragma unroll 4
        for (int d = 0; d < 128; d++)
            acc = fmaf(in_proj_w[j * 128 + d], mixer_b[d], acc);
        g_bias[j] = acc;
    } else if (idx < NW + DPROJ + DINNER) {
        int i = idx - NW - DPROJ;
        float acc = 0.f;
        #pragma unroll 4
        for (int d = 0; d < 128; d++)
            acc = fmaf(out_proj_w[d * DINNER + i], head_w[d], acc);
        g_v[i] = acc;
    }
}

// =====================================================================
// prep2: W (k<128) -> fp16 chunk tiles [jc][n(144)][k(128)]
// =====================================================================
__global__ void prep2_kernel() {
    int idx = blockIdx.x * blockDim.x + threadIdx.x;
    const int NH = NJC * TN * TK;
    if (idx < NH) {
        int k = idx & 127;
        int t = idx >> 7;
        int n = t % TN;
        int jc = t / TN;
        int j = jc * TN + n;
        float val = (j < DPROJ) ? g_W[j * NCH + k] : 0.f;
        g_Wh[idx] = __float2half(val);
    } else if (idx < NH + 576) {
        int j = idx - NH;
        g_Wcol[j] = (j < DPROJ) ? g_W[j * NCH + 128] : 0.f;
    } else if (idx < NH + 1152) {
        int j = idx - NH - 576;
        g_biasP[j] = (j < DPROJ) ? g_bias[j] : 0.f;
    }
}

// =====================================================================
// xh_kernel: transpose+convert x -> fp16 [b][t][k]
// =====================================================================
__global__ void __launch_bounds__(256)
xh_kernel(const float* __restrict__ x) {
    __shared__ float tile[128][65];
    const int tt0 = blockIdx.x * 64, b = blockIdx.y;
    const float* xb = x + (size_t)b * (NCH * NT);

    for (int i = threadIdx.x; i < 128 * 64; i += 256) {
        int c = i >> 6, t = i & 63;
        int gt = tt0 + t;
        tile[c][t] = (gt < NT) ? xb[(size_t)c * NT + gt] : 0.f;
    }
    __syncthreads();
    __half* dst = g_xh + ((size_t)b * 256 + tt0) * 128;
    for (int i = threadIdx.x; i < 64 * 64; i += 256) {
        int t = i >> 6, cp = i & 63;
        __half2 h = __floats2half2_rn(tile[2 * cp][t], tile[2 * cp + 1][t]);
        *(__half2*)(dst + (size_t)t * 128 + 2 * cp) = h;
    }
}

// =====================================================================
// gemm_mma: 512 threads, warp grid 8(M)x2(N): 16x72 per warp, 36 acc
//   regs -> 32 warps/SM. Single-pass fp16, same tiles/epilogue.
// =====================================================================
__global__ void __launch_bounds__(512, 2)
gemm_mma(const float* __restrict__ x,
         const float* __restrict__ dt_bias,
         const float* __restrict__ A_log) {
    extern __shared__ __align__(16) unsigned char sm[];
    const uint32_t sbase = smem_u32(sm);
    const int tid = threadIdx.x;
    const int wid = tid >> 5, lane = tid & 31;
    const int gid = lane >> 2, tig = lane & 3;
    const int wm = wid & 7, wn = wid >> 3;
    const int tt = blockIdx.x, jc = blockIdx.y, b = blockIdx.z;
    const int t0 = tt * TM;

    // ---- B tile: 16B copies
    {
        const unsigned char* src = (const unsigned char*)(g_Wh + (size_t)jc * (TN * TK));
        for (int i = tid; i < TN * 16; i += 512) {
            int n = i >> 4, q = i & 15;
            *(uint4*)(sm + SM_BH + n * PITCHB + q * 16) = *(const uint4*)(src + n * 256 + q * 16);
        }
    }
    // ---- A tile: 16B copies from pre-converted g_xh
    {
        const uint4* src = (const uint4*)(g_xh + ((size_t)b * 256 + t0) * 128);
        for (int i = tid; i < TM * 16; i += 512) {
            int m = i >> 4, q = i & 15;
            *(uint4*)(sm + SM_AH + m * PITCHB + q * 16) = src[m * 16 + q];
        }
    }
    // ---- epilogue constants
    if (tid < 128) {
        int t = t0 + tid;
        const float* xb = x + (size_t)b * (NCH * NT);
        *(float*)(sm + SM_X128 + tid * 4) = (t < NT) ? xb[(size_t)128 * NT + t] : 0.f;
    }
    if (tid >= 128 && tid < 128 + TN) {
        int i = tid - 128;
        *(float*)(sm + SM_W128 + i * 4) = g_Wcol[jc * TN + i];
        *(float*)(sm + SM_BIAS + i * 4) = g_biasP[jc * TN + i];
    }
    __syncthreads();

    // ---- mainloop: warp computes 16(M) x 72(N) ----
    float acc[9][4];
    #pragma unroll
    for (int ni = 0; ni < 9; ni++)
        #pragma unroll
        for (int q = 0; q < 4; q++) acc[ni][q] = 0.f;

    const uint32_t aOff = (uint32_t)(wm * 16 + (lane & 15)) * PITCHB + (uint32_t)(lane >> 4) * 16;
    const uint32_t bBase = (uint32_t)(wn * 72) * PITCHB;
    const uint32_t bOff  = bBase + (uint32_t)(lane & 15) * PITCHB + (uint32_t)(lane >> 4) * 16;
    const uint32_t b2Off = bBase + (uint32_t)(64 + (lane & 7)) * PITCHB + (uint32_t)((lane >> 3) & 1) * 16;

    const uint32_t Ah = sbase + SM_AH + aOff;
    const uint32_t Bb = sbase + SM_BH + bOff;
    const uint32_t Bb2 = sbase + SM_BH + b2Off;

    #pragma unroll
    for (int kk = 0; kk < NKK; kk++) {
        uint32_t ah[4];
        ldsm4(ah, Ah + kk * 32);
        #pragma unroll
        for (int q = 0; q < 4; q++) {
            uint32_t bb[4];
            ldsm4(bb, Bb + (uint32_t)(q * 16) * PITCHB + kk * 32);
            uint32_t f0[2] = { bb[0], bb[2] };
            uint32_t f1[2] = { bb[1], bb[3] };
            mma16816(acc[2 * q],     ah, f0);
            mma16816(acc[2 * q + 1], ah, f1);
        }
        uint32_t b2[2];
        ldsm2(b2, Bb2 + kk * 32);
        mma16816(acc[8], ah, b2);
    }

    // ---- stage accumulators to smem ----
    __syncthreads();
    float* stage = (float*)sm;
    {
        int r = wm * 16 + gid;
        int cb = wn * 72 + 2 * tig;
        #pragma unroll
        for (int ni = 0; ni < 9; ni++) {
            int c = cb + ni * 8;
            *(float2*)(stage + r * SPITCH + c) = make_float2(acc[ni][0], acc[ni][1]);
            *(float2*)(stage + (r + 8) * SPITCH + c) = make_float2(acc[ni][2], acc[ni][3]);
        }
    }
    __syncthreads();

    // ---- epilogue ----
    const float* xs128 = (const float*)(sm + SM_X128);
    const float* sW = (const float*)(sm + SM_W128);
    const float* sBs = (const float*)(sm + SM_BIAS);
    for (int i = tid; i < TM * (TN / 4); i += 512) {
        int row = i / (TN / 4), q = i % (TN / 4);
        int t = t0 + row;
        int j = jc * TN + 4 * q;
        if (t >= NT) continue;
        const float* sp = stage + row * SPITCH + 4 * q;
        float xk = xs128[row];
        float o0 = fmaf(xk, sW[4 * q + 0], sp[0] + sBs[4 * q + 0]);
        float o1 = fmaf(xk, sW[4 * q + 1], sp[1] + sBs[4 * q + 1]);
        float o2 = fmaf(xk, sW[4 * q + 2], sp[2] + sBs[4 * q + 2]);
        float o3 = fmaf(xk, sW[4 * q + 3], sp[3] + sBs[4 * q + 3]);
        if (j + 3 < 256) {
            o0 = __fdividef(o0, 1.f + __expf(-o0));
            o1 = __fdividef(o1, 1.f + __expf(-o1));
            o2 = __fdividef(o2, 1.f + __expf(-o2));
            o3 = __fdividef(o3, 1.f + __expf(-o3));
            __half2 ha = __floats2half2_rn(o0, o1);
            __half2 hb = __floats2half2_rn(o2, o3);
            uint2 pk = { *(uint32_t*)&ha, *(uint32_t*)&hb };
            *(uint2*)(g_zx + ((size_t)b * NT + t) * ROWH + j) = pk;
        } else if (j + 3 < 544) {
            __half2 ha = __floats2half2_rn(o0, o1);
            __half2 hb = __floats2half2_rn(o2, o3);
            uint2 pk = { *(uint32_t*)&ha, *(uint32_t*)&hb };
            *(uint2*)(g_zx + ((size_t)b * NT + t) * ROWH + j) = pk;
        } else if (j == 544) {
            float ov[4] = { o0, o1, o2, o3 };
            float* dst = g_dtA + ((size_t)b * NT + t) * 8;
            float4 lo, hi;
            float r0 = ov[0] + dt_bias[0];
            float d0 = (r0 > 15.f) ? r0 : __logf(1.f + __expf(r0));
            lo.x = d0; lo.y = __expf(d0 * -__expf(A_log[0]));
            float r1 = ov[1] + dt_bias[1];
            float d1 = (r1 > 15.f) ? r1 : __logf(1.f + __expf(r1));
            lo.z = d1; lo.w = __expf(d1 * -__expf(A_log[1]));
            float r2 = ov[2] + dt_bias[2];
            float d2 = (r2 > 15.f) ? r2 : __logf(1.f + __expf(r2));
            hi.x = d2; hi.y = __expf(d2 * -__expf(A_log[2]));
            float r3 = ov[3] + dt_bias[3];
            float d3 = (r3 > 15.f) ? r3 : __logf(1.f + __expf(r3));
            hi.z = d3; hi.w = __expf(d3 * -__expf(A_log[3]));
            *(float4*)(dst) = lo;
            *(float4*)(dst + 4) = hi;
        }
    }
}

// =====================================================================
// scan: R12 version (measured 171us)
// =====================================================================
__global__ void __launch_bounds__(160, 4)
scan_kernel(const float* __restrict__ conv_w, const float* __restrict__ conv_b,
            const float* __restrict__ Dp) {
    const int b = blockIdx.x;
    const int tid = threadIdx.x;
    const int c0 = 2 * tid;
    const int h = tid >> 5;

    __shared__ uint32_t sXBC[RD][144];
    __shared__ uint32_t sGZ[RD][128];
    __shared__ float    sDTA[RD][8];
    __shared__ __align__(8) float2 sB2[2][DSTATE];
    __shared__ __align__(8) float2 sC2[2][DSTATE];

    const bool isConv = (tid < 144);
    const bool isScan = (tid < 128);
    const bool isDt   = (tid >= 144 && tid < 148);

    ull wk0 = 0, wk1 = 0, wk2_ = 0, wk3 = 0, cb2 = 0;
    if (isConv) {
        wk0 = pack2(conv_w[c0 * 4 + 0], conv_w[(c0 + 1) * 4 + 0]);
        wk1 = pack2(conv_w[c0 * 4 + 1], conv_w[(c0 + 1) * 4 + 1]);
        wk2_ = pack2(conv_w[c0 * 4 + 2], conv_w[(c0 + 1) * 4 + 2]);
        wk3 = pack2(conv_w[c0 * 4 + 3], conv_w[(c0 + 1) * 4 + 3]);
        cb2 = pack2(conv_b[c0], conv_b[c0 + 1]);
    }
    ull h1 = 0ULL, h2 = 0ULL, h3 = 0ULL;

    ull D2 = 0ULL;
    if (isScan) D2 = dup2(Dp[h]);

    ull s2[DSTATE];
    #pragma unroll
    for (int n = 0; n < DSTATE; n++) s2[n] = 0ULL;

    const __half* zx = g_zx + (size_t)b * NT * ROWH;
    const float* dtp = g_dtA + (size_t)b * NT * 8;
    __half* gout = g_gout + (size_t)b * NT * 256;

    uint32_t aXBC = isConv ? smem_u32(&sXBC[0][tid]) : 0;
    uint32_t aGZ  = isScan ? smem_u32(&sGZ[0][tid]) : 0;
    uint32_t aDTA = isDt   ? smem_u32(&sDTA[0][2 * (tid - 144)]) : 0;

    #pragma unroll
    for (int d = 0; d < RD - 1; d++) {
        if (isConv) CP_ASYNC4(aXBC + d * 144 * 4, (const void*)(zx + (size_t)d * ROWH + 256 + c0));
        if (isScan) CP_ASYNC4(aGZ + d * 128 * 4, (const void*)(zx + (size_t)d * ROWH + c0));
        if (isDt)   CP_ASYNC8(aDTA + d * 8 * 4, (const void*)(dtp + (size_t)d * 8 + 2 * (tid - 144)));
        CP_COMMIT();
    }

    for (int t = 0; t < NT; t++) {
        const int slot = t & (RD - 1);
        const int buf = t & 1;

        CP_WAIT6();

        float cs0 = 0.f, cs1 = 0.f;
        if (isConv) {
            uint32_t rawu = sXBC[slot][tid];
            float2 fr = __half22float2(*(const __half2*)&rawu);
            ull r2 = pack2(fr.x, fr.y);
            ull cv2 = ffma2(wk3, r2, ffma2(wk2_, h1, ffma2(wk1, h2, ffma2(wk0, h3, cb2))));
            h3 = h2; h2 = h1; h1 = r2;
            float2 cv = unpk2(cv2);
            cs0 = __fdividef(cv.x, 1.f + __expf(-cv.x));
            cs1 = __fdividef(cv.y, 1.f + __expf(-cv.y));
            if (tid >= 128) {
                if (tid < 136) {
                    int k = 2 * (tid - 128);
                    sB2[buf][k]     = make_float2(cs0, cs0);
                    sB2[buf][k + 1] = make_float2(cs1, cs1);
                } else {
                    int k = 2 * (tid - 136);
                    sC2[buf][k]     = make_float2(cs0, cs0);
                    sC2[buf][k + 1] = make_float2(cs1, cs1);
                }
            }
        }
        __syncthreads();

        if (isScan) {
            float2 dtA = *(const float2*)&sDTA[slot][2 * h];
            uint32_t gzu = sGZ[slot][tid];
            float2 gz = __half22float2(*(const __half2*)&gzu);
            ull dA2 = dup2(dtA.y);
            ull dx2 = pack2(dtA.x * cs0, dtA.x * cs1);
            ull ya = fmul2(D2, pack2(cs0, cs1));
            ull yb = 0ULL;
            #pragma unroll
            for (int n = 0; n < DSTATE; n += 2) {
                s2[n]     = ffma2(s2[n],     dA2, fmul2(dx2, *(const ull*)&sB2[buf][n]));
                ya        = ffma2(s2[n],     *(const ull*)&sC2[buf][n], ya);
                s2[n + 1] = ffma2(s2[n + 1], dA2, fmul2(dx2, *(const ull*)&sB2[buf][n + 1]));
                yb        = ffma2(s2[n + 1], *(const ull*)&sC2[buf][n + 1], yb);
            }
            float2 yy = unpk2(ya);
            float2 yz = unpk2(yb);
            float g0 = (yy.x + yz.x) * gz.x;
            float g1 = (yy.y + yz.y) * gz.y;
            __half2 gh = __floats2half2_rn(g0, g1);
            *(__half2*)(gout + (size_t)t * 256 + c0) = gh;
        }

        {
            int s = t + RD - 1;
            if (s < NT) {
                int sl = s & (RD - 1);
                if (isConv) CP_ASYNC4(aXBC + sl * 144 * 4, (const void*)(zx + (size_t)s * ROWH + 256 + c0));
                if (isScan) CP_ASYNC4(aGZ + sl * 128 * 4, (const void*)(zx + (size_t)s * ROWH + c0));
                if (isDt)   CP_ASYNC8(aDTA + sl * 8 * 4, (const void*)(dtp + (size_t)s * 8 + 2 * (tid - 144)));
            }
            CP_COMMIT();
        }
    }
}

// =====================================================================
// combine: fully parallel RMS sums + rsqrt + pool + head
// =====================================================================
__global__ void __launch_bounds__(256)
combine_kernel(const float* __restrict__ norm_w,
               const float* __restrict__ head_b, float* __restrict__ out) {
    const int b = blockIdx.x;
    const int tid = threadIdx.x;
    const int lane = tid & 31, wid = tid >> 5;

    __shared__ float s_nwv[256];
    __shared__ float sred[8];

    s_nwv[tid] = norm_w[tid] * g_v[tid];
    __syncthreads();

    const __half* gp = g_gout + (size_t)b * NT * 256;
    float facc = 0.f;

    for (int t = wid; t < NT; t += 8) {
        const uint2* rowp = (const uint2*)(gp + (size_t)t * 256);
        uint2 u0 = rowp[2 * lane];
        uint2 u1 = rowp[2 * lane + 1];
        const float* nv = s_nwv + 8 * lane;
        float2 a = __half22float2(*(__half2*)&u0.x);
        float2 c = __half22float2(*(__half2*)&u0.y);
        float2 d = __half22float2(*(__half2*)&u1.x);
        float2 e = __half22float2(*(__half2*)&u1.y);
        float SS = a.x * a.x + a.y * a.y + c.x * c.x + c.y * c.y
                 + d.x * d.x + d.y * d.y + e.x * e.x + e.y * e.y;
        float P = a.x * nv[0] + a.y * nv[1] + c.x * nv[2] + c.y * nv[3]
                + d.x * nv[4] + d.y * nv[5] + e.x * nv[6] + e.y * nv[7];
        #pragma unroll
        for (int o = 16; o > 0; o >>= 1) {
            SS += __shfl_xor_sync(0xffffffffu, SS, o);
            P  += __shfl_xor_sync(0xffffffffu, P, o);
        }
        if (lane == 0)
            facc = fmaf(P, rsqrtf(SS * (1.f / 256.f) + EPSV), facc);
    }

    if (lane == 0) sred[wid] = facc;
    __syncthreads();
    if (tid == 0) {
        float tot = 0.f;
        #pragma unroll
        for (int w = 0; w < 8; w++) tot += sred[w];
        out[b] = tot * (1.f / (float)NT) + head_b[0];
    }
}

// =====================================================================
// launch
// =====================================================================
extern "C" void kernel_launch(void* const* d_in, const int* in_sizes, int n_in,
                              void* d_out, int out_size) {
    const float* x          = (const float*)d_in[0];
    const float* mixer_w    = (const float*)d_in[1];
    const float* mixer_b    = (const float*)d_in[2];
    const float* in_proj_w  = (const float*)d_in[3];
    const float* conv_w     = (const float*)d_in[4];
    const float* conv_b     = (const float*)d_in[5];
    const float* dt_bias    = (const float*)d_in[6];
    const float* A_log      = (const float*)d_in[7];
    const float* Dvec       = (const float*)d_in[8];
    const float* norm_w     = (const float*)d_in[9];
    const float* out_proj_w = (const float*)d_in[10];
    const float* head_w     = (const float*)d_in[11];
    const float* head_b     = (const float*)d_in[12];
    float* out = (float*)d_out;

    {
        int total = DPROJ * NCH + DPROJ + DINNER;
        prep1_kernel<<<(total + 255) / 256, 256>>>(in_proj_w, mixer_w, mixer_b,
                                                   out_proj_w, head_w);
    }
    {
        int total = NJC * TN * TK + 1152;
        prep2_kernel<<<(total + 255) / 256, 256>>>();
    }
    {
        dim3 grid(4, BSZ);
        xh_kernel<<<grid, 256>>>(x);
    }
    {
        cudaFuncSetAttribute(gemm_mma,
                             cudaFuncAttributeMaxDynamicSharedMemorySize, SMEM_SZ);
        dim3 grid(2, NJC, BSZ);
        gemm_mma<<<grid, 512, SMEM_SZ>>>(x, dt_bias, A_log);
    }
    scan_kernel<<<BSZ, 160>>>(conv_w, conv_b, Dvec);
    combine_kernel<<<BSZ, 256>>>(norm_w, head_b, out);
}

// round 16
// speedup vs baseline: 1.3147x; 1.0314x over previous
#include <cuda_runtime.h>
#include <cuda_fp16.h>
#include <cstdint>

// ---------------- model constants ----------------
#define BSZ      512
#define NCH      129
#define NT       250
#define DINNER   256
#define DSTATE   16
#define NHEADS   4
#define CONVDIM  288
#define DPROJ    548
#define EPSV     1e-5f
#define ROWH     544        // gz(256)+xBC raw(288) fp16 per row

// GEMM tiling
#define TM     128
#define TN     144
#define TK     128
#define NJC    4
#define NKK    8
#define PITCHB 272
#define HSP    152          // half-stage pitch (halves); row = 304 B (16B mult)

// scan prefetch ring
#define RD     8

// ---------------- device scratch ----------------
typedef unsigned long long ull;
__device__ float g_W[DPROJ * NCH];
__device__ float g_Wp[4][DPROJ * NCH];     // prep1 partials
__device__ float g_bias[DPROJ];
__device__ float g_v[DINNER];
__device__ __align__(16) __half g_xh[(size_t)BSZ * 256 * 128];
__device__ __align__(16) __half g_zx[(size_t)BSZ * NT * ROWH];
__device__ __align__(16) float g_dtA[(size_t)BSZ * NT * 8];
__device__ __align__(16) __half g_gout[(size_t)BSZ * NT * 256];
__device__ __align__(16) __half g_Wh[NJC * TN * TK];
__device__ float g_Wcol[576];
__device__ float g_biasP[576];

// ---------------- GEMM smem layout (bytes) ----------------
#define SM_AH    0
#define SM_BH    34816
#define SM_X128  75776
#define SM_W128  76288
#define SM_BIAS  76864
#define SMEM_SZ  77440
// half stage (post-mainloop) reuses [0, 38912) — disjoint from constants.

// ---------------- packed f32x2 helpers ----------------
__device__ __forceinline__ ull dup2(float v) {
    ull r; asm("mov.b64 %0, {%1, %1};" : "=l"(r) : "f"(v)); return r;
}
__device__ __forceinline__ ull pack2(float lo, float hi) {
    ull r; asm("mov.b64 %0, {%1, %2};" : "=l"(r) : "f"(lo), "f"(hi)); return r;
}
__device__ __forceinline__ ull ffma2(ull a, ull b, ull c) {
    ull d; asm("fma.rn.f32x2 %0, %1, %2, %3;" : "=l"(d) : "l"(a), "l"(b), "l"(c)); return d;
}
__device__ __forceinline__ ull fmul2(ull a, ull b) {
    ull d; asm("mul.rn.f32x2 %0, %1, %2;" : "=l"(d) : "l"(a), "l"(b)); return d;
}
__device__ __forceinline__ float2 unpk2(ull v) {
    float2 f; asm("mov.b64 {%0, %1}, %2;" : "=f"(f.x), "=f"(f.y) : "l"(v)); return f;
}

// ---------------- mma / ldmatrix / cp.async ----------------
__device__ __forceinline__ void mma16816(float* d, const uint32_t* a, const uint32_t* b) {
    asm volatile(
        "mma.sync.aligned.m16n8k16.row.col.f32.f16.f16.f32 "
        "{%0,%1,%2,%3}, {%4,%5,%6,%7}, {%8,%9}, {%0,%1,%2,%3};"
        : "+f"(d[0]), "+f"(d[1]), "+f"(d[2]), "+f"(d[3])
        : "r"(a[0]), "r"(a[1]), "r"(a[2]), "r"(a[3]), "r"(b[0]), "r"(b[1]));
}
__device__ __forceinline__ void ldsm4(uint32_t* r, uint32_t addr) {
    asm volatile("ldmatrix.sync.aligned.m8n8.x4.shared.b16 {%0,%1,%2,%3}, [%4];"
        : "=r"(r[0]), "=r"(r[1]), "=r"(r[2]), "=r"(r[3]) : "r"(addr));
}
__device__ __forceinline__ void ldsm2(uint32_t* r, uint32_t addr) {
    asm volatile("ldmatrix.sync.aligned.m8n8.x2.shared.b16 {%0,%1}, [%2];"
        : "=r"(r[0]), "=r"(r[1]) : "r"(addr));
}
__device__ __forceinline__ uint32_t smem_u32(const void* p) {
    uint32_t a;
    asm("{ .reg .u64 t; cvta.to.shared.u64 t, %1; cvt.u32.u64 %0, t; }" : "=r"(a) : "l"(p));
    return a;
}
#define CP_ASYNC4(sa, gp) asm volatile("cp.async.ca.shared.global [%0], [%1], 4;" :: "r"(sa), "l"(gp) : "memory")
#define CP_ASYNC8(sa, gp) asm volatile("cp.async.ca.shared.global [%0], [%1], 8;" :: "r"(sa), "l"(gp) : "memory")
#define CP_COMMIT()       asm volatile("cp.async.commit_group;" ::: "memory")
#define CP_WAIT6()        asm volatile("cp.async.wait_group 6;" ::: "memory")

// =====================================================================
// prep1a: W partials over 4 d-chunks (grid ~1105 — fills the chip)
// =====================================================================
__global__ void prep1a_kernel(const float* __restrict__ in_proj_w,
                              const float* __restrict__ mixer_w) {
    int idx = blockIdx.x * blockDim.x + threadIdx.x;
    const int NW = DPROJ * NCH;
    if (idx >= 4 * NW) return;
    int chunk = idx / NW;
    int w = idx - chunk * NW;
    int j = w / NCH, c = w - j * NCH;
    int d0 = chunk * 32;
    float a0 = 0.f, a1 = 0.f, a2 = 0.f, a3 = 0.f;
    #pragma unroll 8
    for (int d = 0; d < 32; d += 4) {
        a0 = fmaf(in_proj_w[j * 128 + d0 + d + 0], mixer_w[(d0 + d + 0) * NCH + c], a0);
        a1 = fmaf(in_proj_w[j * 128 + d0 + d + 1], mixer_w[(d0 + d + 1) * NCH + c], a1);
        a2 = fmaf(in_proj_w[j * 128 + d0 + d + 2], mixer_w[(d0 + d + 2) * NCH + c], a2);
        a3 = fmaf(in_proj_w[j * 128 + d0 + d + 3], mixer_w[(d0 + d + 3) * NCH + c], a3);
    }
    g_Wp[chunk][w] = (a0 + a1) + (a2 + a3);
}

// =====================================================================
// prep1b: sum partials; bias; v
// =====================================================================
__global__ void prep1b_kernel(const float* __restrict__ in_proj_w,
                              const float* __restrict__ mixer_b,
                              const float* __restrict__ out_proj_w,
                              const float* __restrict__ head_w) {
    int idx = blockIdx.x * blockDim.x + threadIdx.x;
    const int NW = DPROJ * NCH;
    if (idx < NW) {
        g_W[idx] = (g_Wp[0][idx] + g_Wp[1][idx]) + (g_Wp[2][idx] + g_Wp[3][idx]);
    } else if (idx < NW + DPROJ) {
        int j = idx - NW;
        float acc = 0.f;
        #pragma unroll 4
        for (int d = 0; d < 128; d++)
            acc = fmaf(in_proj_w[j * 128 + d], mixer_b[d], acc);
        g_bias[j] = acc;
    } else if (idx < NW + DPROJ + DINNER) {
        int i = idx - NW - DPROJ;
        float acc = 0.f;
        #pragma unroll 4
        for (int d = 0; d < 128; d++)
            acc = fmaf(out_proj_w[d * DINNER + i], head_w[d], acc);
        g_v[i] = acc;
    }
}

// =====================================================================
// prep2: W (k<128) -> fp16 chunk tiles [jc][n(144)][k(128)]
// =====================================================================
__global__ void prep2_kernel() {
    int idx = blockIdx.x * blockDim.x + threadIdx.x;
    const int NH = NJC * TN * TK;
    if (idx < NH) {
        int k = idx & 127;
        int t = idx >> 7;
        int n = t % TN;
        int jc = t / TN;
        int j = jc * TN + n;
        float val = (j < DPROJ) ? g_W[j * NCH + k] : 0.f;
        g_Wh[idx] = __float2half(val);
    } else if (idx < NH + 576) {
        int j = idx - NH;
        g_Wcol[j] = (j < DPROJ) ? g_W[j * NCH + 128] : 0.f;
    } else if (idx < NH + 1152) {
        int j = idx - NH - 576;
        g_biasP[j] = (j < DPROJ) ? g_bias[j] : 0.f;
    }
}

// =====================================================================
// xh_kernel: transpose+convert x -> fp16 [b][t][k]
// =====================================================================
__global__ void __launch_bounds__(256)
xh_kernel(const float* __restrict__ x) {
    __shared__ float tile[128][65];
    const int tt0 = blockIdx.x * 64, b = blockIdx.y;
    const float* xb = x + (size_t)b * (NCH * NT);

    for (int i = threadIdx.x; i < 128 * 64; i += 256) {
        int c = i >> 6, t = i & 63;
        int gt = tt0 + t;
        tile[c][t] = (gt < NT) ? xb[(size_t)c * NT + gt] : 0.f;
    }
    __syncthreads();
    __half* dst = g_xh + ((size_t)b * 256 + tt0) * 128;
    for (int i = threadIdx.x; i < 64 * 64; i += 256) {
        int t = i >> 6, cp = i & 63;
        __half2 h = __floats2half2_rn(tile[2 * cp][t], tile[2 * cp + 1][t]);
        *(__half2*)(dst + (size_t)t * 128 + 2 * cp) = h;
    }
}

// =====================================================================
// gemm_mma: 512 thr, warp 16x72; register epilogue + fp16 staging
// =====================================================================
__global__ void __launch_bounds__(512, 2)
gemm_mma(const float* __restrict__ x,
         const float* __restrict__ dt_bias,
         const float* __restrict__ A_log) {
    extern __shared__ __align__(16) unsigned char sm[];
    const uint32_t sbase = smem_u32(sm);
    const int tid = threadIdx.x;
    const int wid = tid >> 5, lane = tid & 31;
    const int gid = lane >> 2, tig = lane & 3;
    const int wm = wid & 7, wn = wid >> 3;
    const int tt = blockIdx.x, jc = blockIdx.y, b = blockIdx.z;
    const int t0 = tt * TM;

    // ---- B tile
    {
        const unsigned char* src = (const unsigned char*)(g_Wh + (size_t)jc * (TN * TK));
        for (int i = tid; i < TN * 16; i += 512) {
            int n = i >> 4, q = i & 15;
            *(uint4*)(sm + SM_BH + n * PITCHB + q * 16) = *(const uint4*)(src + n * 256 + q * 16);
        }
    }
    // ---- A tile
    {
        const uint4* src = (const uint4*)(g_xh + ((size_t)b * 256 + t0) * 128);
        for (int i = tid; i < TM * 16; i += 512) {
            int m = i >> 4, q = i & 15;
            *(uint4*)(sm + SM_AH + m * PITCHB + q * 16) = src[m * 16 + q];
        }
    }
    // ---- epilogue constants (beyond stage region)
    if (tid < 128) {
        int t = t0 + tid;
        const float* xb = x + (size_t)b * (NCH * NT);
        *(float*)(sm + SM_X128 + tid * 4) = (t < NT) ? xb[(size_t)128 * NT + t] : 0.f;
    }
    if (tid >= 128 && tid < 128 + TN) {
        int i = tid - 128;
        *(float*)(sm + SM_W128 + i * 4) = g_Wcol[jc * TN + i];
        *(float*)(sm + SM_BIAS + i * 4) = g_biasP[jc * TN + i];
    }
    __syncthreads();

    // ---- mainloop: warp computes 16(M) x 72(N) ----
    float acc[9][4];
    #pragma unroll
    for (int ni = 0; ni < 9; ni++)
        #pragma unroll
        for (int q = 0; q < 4; q++) acc[ni][q] = 0.f;

    const uint32_t aOff = (uint32_t)(wm * 16 + (lane & 15)) * PITCHB + (uint32_t)(lane >> 4) * 16;
    const uint32_t bBase = (uint32_t)(wn * 72) * PITCHB;
    const uint32_t bOff  = bBase + (uint32_t)(lane & 15) * PITCHB + (uint32_t)(lane >> 4) * 16;
    const uint32_t b2Off = bBase + (uint32_t)(64 + (lane & 7)) * PITCHB + (uint32_t)((lane >> 3) & 1) * 16;

    const uint32_t Ah = sbase + SM_AH + aOff;
    const uint32_t Bb = sbase + SM_BH + bOff;
    const uint32_t Bb2 = sbase + SM_BH + b2Off;

    #pragma unroll
    for (int kk = 0; kk < NKK; kk++) {
        uint32_t ah[4];
        ldsm4(ah, Ah + kk * 32);
        #pragma unroll
        for (int q = 0; q < 4; q++) {
            uint32_t bb[4];
            ldsm4(bb, Bb + (uint32_t)(q * 16) * PITCHB + kk * 32);
            uint32_t f0[2] = { bb[0], bb[2] };
            uint32_t f1[2] = { bb[1], bb[3] };
            mma16816(acc[2 * q],     ah, f0);
            mma16816(acc[2 * q + 1], ah, f1);
        }
        uint32_t b2[2];
        ldsm2(b2, Bb2 + kk * 32);
        mma16816(acc[8], ah, b2);
    }

    // ---- register epilogue: fixup + silu/dt in regs, stage as fp16 ----
    __syncthreads();   // all LDSM done; A/B smem now reusable as stage
    {
        __half* hstage = (__half*)sm;            // [128][HSP]
        const float* xs128 = (const float*)(sm + SM_X128);
        const float* sW = (const float*)(sm + SM_W128);
        const float* sBs = (const float*)(sm + SM_BIAS);
        const int r0 = wm * 16 + gid;
        const float xk0 = xs128[r0], xk1 = xs128[r0 + 8];
        #pragma unroll
        for (int ni = 0; ni < 9; ni++) {
            int c = wn * 72 + ni * 8 + 2 * tig;
            int j = jc * TN + c;
            float W0 = sW[c], W1 = sW[c + 1];
            float b0 = sBs[c], b1 = sBs[c + 1];
            float o00 = fmaf(xk0, W0, acc[ni][0] + b0);
            float o01 = fmaf(xk0, W1, acc[ni][1] + b1);
            float o10 = fmaf(xk1, W0, acc[ni][2] + b0);
            float o11 = fmaf(xk1, W1, acc[ni][3] + b1);
            if (j < 256) {
                o00 = __fdividef(o00, 1.f + __expf(-o00));
                o01 = __fdividef(o01, 1.f + __expf(-o01));
                o10 = __fdividef(o10, 1.f + __expf(-o10));
                o11 = __fdividef(o11, 1.f + __expf(-o11));
            }
            if (j < 544) {
                *(__half2*)(hstage + (size_t)r0 * HSP + c) = __floats2half2_rn(o00, o01);
                *(__half2*)(hstage + (size_t)(r0 + 8) * HSP + c) = __floats2half2_rn(o10, o11);
            } else if (j < 548) {
                // dt columns (jc=3, wn=1, ni=5, tig 0/1): write (dt,dA) fp32
                int h0 = j - 544;
                float vv[2][2] = { { o00, o01 }, { o10, o11 } };
                #pragma unroll
                for (int rr = 0; rr < 2; rr++) {
                    int t = t0 + r0 + rr * 8;
                    if (t < NT) {
                        float* dst = g_dtA + ((size_t)b * NT + t) * 8;
                        #pragma unroll
                        for (int hh = 0; hh < 2; hh++) {
                            int hq = h0 + hh;
                            float rv = vv[rr][hh] + dt_bias[hq];
                            float dt = (rv > 15.f) ? rv : __logf(1.f + __expf(rv));
                            float dA = __expf(dt * -__expf(A_log[hq]));
                            *(float2*)(dst + 2 * hq) = make_float2(dt, dA);
                        }
                    }
                }
            }
        }
    }
    __syncthreads();

    // ---- coalesced copy: fp16 stage -> g_zx ----
    {
        const __half* hstage = (const __half*)sm;
        for (int i = tid; i < TM * 18; i += 512) {
            int row = i / 18, q = i % 18;
            int j = jc * TN + q * 8;
            int t = t0 + row;
            if (t >= NT || j >= 544) continue;
            *(uint4*)(g_zx + ((size_t)b * NT + t) * ROWH + j) =
                *(const uint4*)(hstage + (size_t)row * HSP + q * 8);
        }
    }
}

// =====================================================================
// scan: R12 version (measured 171us)
// =====================================================================
__global__ void __launch_bounds__(160, 4)
scan_kernel(const float* __restrict__ conv_w, const float* __restrict__ conv_b,
            const float* __restrict__ Dp) {
    const int b = blockIdx.x;
    const int tid = threadIdx.x;
    const int c0 = 2 * tid;
    const int h = tid >> 5;

    __shared__ uint32_t sXBC[RD][144];
    __shared__ uint32_t sGZ[RD][128];
    __shared__ float    sDTA[RD][8];
    __shared__ __align__(8) float2 sB2[2][DSTATE];
    __shared__ __align__(8) float2 sC2[2][DSTATE];

    const bool isConv = (tid < 144);
    const bool isScan = (tid < 128);
    const bool isDt   = (tid >= 144 && tid < 148);

    ull wk0 = 0, wk1 = 0, wk2_ = 0, wk3 = 0, cb2 = 0;
    if (isConv) {
        wk0 = pack2(conv_w[c0 * 4 + 0], conv_w[(c0 + 1) * 4 + 0]);
        wk1 = pack2(conv_w[c0 * 4 + 1], conv_w[(c0 + 1) * 4 + 1]);
        wk2_ = pack2(conv_w[c0 * 4 + 2], conv_w[(c0 + 1) * 4 + 2]);
        wk3 = pack2(conv_w[c0 * 4 + 3], conv_w[(c0 + 1) * 4 + 3]);
        cb2 = pack2(conv_b[c0], conv_b[c0 + 1]);
    }
    ull h1 = 0ULL, h2 = 0ULL, h3 = 0ULL;

    ull D2 = 0ULL;
    if (isScan) D2 = dup2(Dp[h]);

    ull s2[DSTATE];
    #pragma unroll
    for (int n = 0; n < DSTATE; n++) s2[n] = 0ULL;

    const __half* zx = g_zx + (size_t)b * NT * ROWH;
    const float* dtp = g_dtA + (size_t)b * NT * 8;
    __half* gout = g_gout + (size_t)b * NT * 256;

    uint32_t aXBC = isConv ? smem_u32(&sXBC[0][tid]) : 0;
    uint32_t aGZ  = isScan ? smem_u32(&sGZ[0][tid]) : 0;
    uint32_t aDTA = isDt   ? smem_u32(&sDTA[0][2 * (tid - 144)]) : 0;

    #pragma unroll
    for (int d = 0; d < RD - 1; d++) {
        if (isConv) CP_ASYNC4(aXBC + d * 144 * 4, (const void*)(zx + (size_t)d * ROWH + 256 + c0));
        if (isScan) CP_ASYNC4(aGZ + d * 128 * 4, (const void*)(zx + (size_t)d * ROWH + c0));
        if (isDt)   CP_ASYNC8(aDTA + d * 8 * 4, (const void*)(dtp + (size_t)d * 8 + 2 * (tid - 144)));
        CP_COMMIT();
    }

    for (int t = 0; t < NT; t++) {
        const int slot = t & (RD - 1);
        const int buf = t & 1;

        CP_WAIT6();

        float cs0 = 0.f, cs1 = 0.f;
        if (isConv) {
            uint32_t rawu = sXBC[slot][tid];
            float2 fr = __half22float2(*(const __half2*)&rawu);
            ull r2 = pack2(fr.x, fr.y);
            ull cv2 = ffma2(wk3, r2, ffma2(wk2_, h1, ffma2(wk1, h2, ffma2(wk0, h3, cb2))));
            h3 = h2; h2 = h1; h1 = r2;
            float2 cv = unpk2(cv2);
            cs0 = __fdividef(cv.x, 1.f + __expf(-cv.x));
            cs1 = __fdividef(cv.y, 1.f + __expf(-cv.y));
            if (tid >= 128) {
                if (tid < 136) {
                    int k = 2 * (tid - 128);
                    sB2[buf][k]     = make_float2(cs0, cs0);
                    sB2[buf][k + 1] = make_float2(cs1, cs1);
                } else {
                    int k = 2 * (tid - 136);
                    sC2[buf][k]     = make_float2(cs0, cs0);
                    sC2[buf][k + 1] = make_float2(cs1, cs1);
                }
            }
        }
        __syncthreads();

        if (isScan) {
            float2 dtA = *(const float2*)&sDTA[slot][2 * h];
            uint32_t gzu = sGZ[slot][tid];
            float2 gz = __half22float2(*(const __half2*)&gzu);
            ull dA2 = dup2(dtA.y);
            ull dx2 = pack2(dtA.x * cs0, dtA.x * cs1);
            ull ya = fmul2(D2, pack2(cs0, cs1));
            ull yb = 0ULL;
            #pragma unroll
            for (int n = 0; n < DSTATE; n += 2) {
                s2[n]     = ffma2(s2[n],     dA2, fmul2(dx2, *(const ull*)&sB2[buf][n]));
                ya        = ffma2(s2[n],     *(const ull*)&sC2[buf][n], ya);
                s2[n + 1] = ffma2(s2[n + 1], dA2, fmul2(dx2, *(const ull*)&sB2[buf][n + 1]));
                yb        = ffma2(s2[n + 1], *(const ull*)&sC2[buf][n + 1], yb);
            }
            float2 yy = unpk2(ya);
            float2 yz = unpk2(yb);
            float g0 = (yy.x + yz.x) * gz.x;
            float g1 = (yy.y + yz.y) * gz.y;
            __half2 gh = __floats2half2_rn(g0, g1);
            *(__half2*)(gout + (size_t)t * 256 + c0) = gh;
        }

        {
            int s = t + RD - 1;
            if (s < NT) {
                int sl = s & (RD - 1);
                if (isConv) CP_ASYNC4(aXBC + sl * 144 * 4, (const void*)(zx + (size_t)s * ROWH + 256 + c0));
                if (isScan) CP_ASYNC4(aGZ + sl * 128 * 4, (const void*)(zx + (size_t)s * ROWH + c0));
                if (isDt)   CP_ASYNC8(aDTA + sl * 8 * 4, (const void*)(dtp + (size_t)s * 8 + 2 * (tid - 144)));
            }
            CP_COMMIT();
        }
    }
}

// =====================================================================
// combine: fully parallel RMS sums + rsqrt + pool + head
// =====================================================================
__global__ void __launch_bounds__(256)
combine_kernel(const float* __restrict__ norm_w,
               const float* __restrict__ head_b, float* __restrict__ out) {
    const int b = blockIdx.x;
    const int tid = threadIdx.x;
    const int lane = tid & 31, wid = tid >> 5;

    __shared__ float s_nwv[256];
    __shared__ float sred[8];

    s_nwv[tid] = norm_w[tid] * g_v[tid];
    __syncthreads();

    const __half* gp = g_gout + (size_t)b * NT * 256;
    float facc = 0.f;

    for (int t = wid; t < NT; t += 8) {
        const uint2* rowp = (const uint2*)(gp + (size_t)t * 256);
        uint2 u0 = rowp[2 * lane];
        uint2 u1 = rowp[2 * lane + 1];
        const float* nv = s_nwv + 8 * lane;
        float2 a = __half22float2(*(__half2*)&u0.x);
        float2 c = __half22float2(*(__half2*)&u0.y);
        float2 d = __half22float2(*(__half2*)&u1.x);
        float2 e = __half22float2(*(__half2*)&u1.y);
        float SS = a.x * a.x + a.y * a.y + c.x * c.x + c.y * c.y
                 + d.x * d.x + d.y * d.y + e.x * e.x + e.y * e.y;
        float P = a.x * nv[0] + a.y * nv[1] + c.x * nv[2] + c.y * nv[3]
                + d.x * nv[4] + d.y * nv[5] + e.x * nv[6] + e.y * nv[7];
        #pragma unroll
        for (int o = 16; o > 0; o >>= 1) {
            SS += __shfl_xor_sync(0xffffffffu, SS, o);
            P  += __shfl_xor_sync(0xffffffffu, P, o);
        }
        if (lane == 0)
            facc = fmaf(P, rsqrtf(SS * (1.f / 256.f) + EPSV), facc);
    }

    if (lane == 0) sred[wid] = facc;
    __syncthreads();
    if (tid == 0) {
        float tot = 0.f;
        #pragma unroll
        for (int w = 0; w < 8; w++) tot += sred[w];
        out[b] = tot * (1.f / (float)NT) + head_b[0];
    }
}

// =====================================================================
// launch
// =====================================================================
extern "C" void kernel_launch(void* const* d_in, const int* in_sizes, int n_in,
                              void* d_out, int out_size) {
    const float* x          = (const float*)d_in[0];
    const float* mixer_w    = (const float*)d_in[1];
    const float* mixer_b    = (const float*)d_in[2];
    const float* in_proj_w  = (const float*)d_in[3];
    const float* conv_w     = (const float*)d_in[4];
    const float* conv_b     = (const float*)d_in[5];
    const float* dt_bias    = (const float*)d_in[6];
    const float* A_log      = (const float*)d_in[7];
    const float* Dvec       = (const float*)d_in[8];
    const float* norm_w     = (const float*)d_in[9];
    const float* out_proj_w = (const float*)d_in[10];
    const float* head_w     = (const float*)d_in[11];
    const float* head_b     = (const float*)d_in[12];
    float* out = (float*)d_out;

    const int NW = DPROJ * NCH;
    prep1a_kernel<<<(4 * NW + 255) / 256, 256>>>(in_proj_w, mixer_w);
    {
        int total = NW + DPROJ + DINNER;
        prep1b_kernel<<<(total + 255) / 256, 256>>>(in_proj_w, mixer_b,
                                                    out_proj_w, head_w);
    }
    {
        int total = NJC * TN * TK + 1152;
        prep2_kernel<<<(total + 255) / 256, 256>>>();
    }
    {
        dim3 grid(4, BSZ);
        xh_kernel<<<grid, 256>>>(x);
    }
    {
        cudaFuncSetAttribute(gemm_mma,
                             cudaFuncAttributeMaxDynamicSharedMemorySize, SMEM_SZ);
        dim3 grid(2, NJC, BSZ);
        gemm_mma<<<grid, 512, SMEM_SZ>>>(x, dt_bias, A_log);
    }
    scan_kernel<<<BSZ, 160>>>(conv_w, conv_b, Dvec);
    combine_kernel<<<BSZ, 256>>>(norm_w, head_b, out);
}

// round 17
// speedup vs baseline: 1.3710x; 1.0428x over previous
#include <cuda_runtime.h>
#include <cuda_fp16.h>
#include <cstdint>

// ---------------- model constants ----------------
#define BSZ      512
#define NCH      129
#define NT       250
#define DINNER   256
#define DSTATE   16
#define NHEADS   4
#define CONVDIM  288
#define DPROJ    548
#define EPSV     1e-5f
#define ROWH     544        // gz(256)+xBC raw(288) fp16 per row

// GEMM tiling
#define TM     128
#define TN     144
#define TK     128
#define NJC    4
#define NKK    8
#define PITCHB 272
#define HSP    152          // half-stage pitch (halves)

// scan prefetch ring
#define RD     8

// ---------------- device scratch ----------------
typedef unsigned long long ull;
__device__ float g_Wp[4][DPROJ * NCH];     // prep1 partials
__device__ float g_v[DINNER];
__device__ __align__(16) __half g_xh[(size_t)BSZ * 256 * 128];
__device__ __align__(16) __half g_zx[(size_t)BSZ * NT * ROWH];
__device__ __align__(16) float g_dtA[(size_t)BSZ * NT * 8];
__device__ __align__(16) __half g_Wh[NJC * TN * TK];
__device__ float g_Wcol[576];
__device__ float g_biasP[576];

// ---------------- GEMM smem layout (bytes) ----------------
#define SM_AH    0
#define SM_BH    34816
#define SM_X128  75776
#define SM_W128  76288
#define SM_BIAS  76864
#define SMEM_SZ  77440
// fp16 stage (post-mainloop) reuses [0, 38912) — disjoint from constants.

// ---------------- packed f32x2 helpers ----------------
__device__ __forceinline__ ull dup2(float v) {
    ull r; asm("mov.b64 %0, {%1, %1};" : "=l"(r) : "f"(v)); return r;
}
__device__ __forceinline__ ull pack2(float lo, float hi) {
    ull r; asm("mov.b64 %0, {%1, %2};" : "=l"(r) : "f"(lo), "f"(hi)); return r;
}
__device__ __forceinline__ ull ffma2(ull a, ull b, ull c) {
    ull d; asm("fma.rn.f32x2 %0, %1, %2, %3;" : "=l"(d) : "l"(a), "l"(b), "l"(c)); return d;
}
__device__ __forceinline__ ull fmul2(ull a, ull b) {
    ull d; asm("mul.rn.f32x2 %0, %1, %2;" : "=l"(d) : "l"(a), "l"(b)); return d;
}
__device__ __forceinline__ float2 unpk2(ull v) {
    float2 f; asm("mov.b64 {%0, %1}, %2;" : "=f"(f.x), "=f"(f.y) : "l"(v)); return f;
}

// ---------------- mma / ldmatrix / cp.async ----------------
__device__ __forceinline__ void mma16816(float* d, const uint32_t* a, const uint32_t* b) {
    asm volatile(
        "mma.sync.aligned.m16n8k16.row.col.f32.f16.f16.f32 "
        "{%0,%1,%2,%3}, {%4,%5,%6,%7}, {%8,%9}, {%0,%1,%2,%3};"
        : "+f"(d[0]), "+f"(d[1]), "+f"(d[2]), "+f"(d[3])
        : "r"(a[0]), "r"(a[1]), "r"(a[2]), "r"(a[3]), "r"(b[0]), "r"(b[1]));
}
__device__ __forceinline__ void ldsm4(uint32_t* r, uint32_t addr) {
    asm volatile("ldmatrix.sync.aligned.m8n8.x4.shared.b16 {%0,%1,%2,%3}, [%4];"
        : "=r"(r[0]), "=r"(r[1]), "=r"(r[2]), "=r"(r[3]) : "r"(addr));
}
__device__ __forceinline__ void ldsm2(uint32_t* r, uint32_t addr) {
    asm volatile("ldmatrix.sync.aligned.m8n8.x2.shared.b16 {%0,%1}, [%2];"
        : "=r"(r[0]), "=r"(r[1]) : "r"(addr));
}
__device__ __forceinline__ uint32_t smem_u32(const void* p) {
    uint32_t a;
    asm("{ .reg .u64 t; cvta.to.shared.u64 t, %1; cvt.u32.u64 %0, t; }" : "=r"(a) : "l"(p));
    return a;
}
#define CP_ASYNC4(sa, gp) asm volatile("cp.async.ca.shared.global [%0], [%1], 4;" :: "r"(sa), "l"(gp) : "memory")
#define CP_ASYNC8(sa, gp) asm volatile("cp.async.ca.shared.global [%0], [%1], 8;" :: "r"(sa), "l"(gp) : "memory")
#define CP_COMMIT()       asm volatile("cp.async.commit_group;" ::: "memory")
#define CP_WAIT6()        asm volatile("cp.async.wait_group 6;" ::: "memory")

// =====================================================================
// prep1a: W partials over 4 d-chunks
// =====================================================================
__global__ void prep1a_kernel(const float* __restrict__ in_proj_w,
                              const float* __restrict__ mixer_w) {
    int idx = blockIdx.x * blockDim.x + threadIdx.x;
    const int NW = DPROJ * NCH;
    if (idx >= 4 * NW) return;
    int chunk = idx / NW;
    int w = idx - chunk * NW;
    int j = w / NCH, c = w - j * NCH;
    int d0 = chunk * 32;
    float a0 = 0.f, a1 = 0.f, a2 = 0.f, a3 = 0.f;
    #pragma unroll 8
    for (int d = 0; d < 32; d += 4) {
        a0 = fmaf(in_proj_w[j * 128 + d0 + d + 0], mixer_w[(d0 + d + 0) * NCH + c], a0);
        a1 = fmaf(in_proj_w[j * 128 + d0 + d + 1], mixer_w[(d0 + d + 1) * NCH + c], a1);
        a2 = fmaf(in_proj_w[j * 128 + d0 + d + 2], mixer_w[(d0 + d + 2) * NCH + c], a2);
        a3 = fmaf(in_proj_w[j * 128 + d0 + d + 3], mixer_w[(d0 + d + 3) * NCH + c], a3);
    }
    g_Wp[chunk][w] = (a0 + a1) + (a2 + a3);
}

// =====================================================================
// prep1b: sum partials -> directly to g_Wh/g_Wcol; bias -> g_biasP; v;
//   plus zero-padding for j in [548, 576)
// =====================================================================
__global__ void prep1b_kernel(const float* __restrict__ in_proj_w,
                              const float* __restrict__ mixer_b,
                              const float* __restrict__ out_proj_w,
                              const float* __restrict__ head_w) {
    int idx = blockIdx.x * blockDim.x + threadIdx.x;
    const int NW = DPROJ * NCH;              // 70692
    const int R1 = NW + DPROJ;               // + bias
    const int R2 = R1 + DINNER;              // + v
    const int NPADW = 28 * 128;              // g_Wh pad rows
    const int R3 = R2 + NPADW;
    const int R4 = R3 + 28;                  // Wcol/bias pads
    if (idx < NW) {
        float val = (g_Wp[0][idx] + g_Wp[1][idx]) + (g_Wp[2][idx] + g_Wp[3][idx]);
        int j = idx / NCH, c = idx - j * NCH;
        int jc = j / TN, n = j - jc * TN;
        if (c < 128) g_Wh[(size_t)jc * (TN * TK) + n * 128 + c] = __float2half(val);
        else         g_Wcol[j] = val;
    } else if (idx < R1) {
        int j = idx - NW;
        float acc = 0.f;
        #pragma unroll 4
        for (int d = 0; d < 128; d++)
            acc = fmaf(in_proj_w[j * 128 + d], mixer_b[d], acc);
        g_biasP[j] = acc;
    } else if (idx < R2) {
        int i = idx - R1;
        float acc = 0.f;
        #pragma unroll 4
        for (int d = 0; d < 128; d++)
            acc = fmaf(out_proj_w[d * DINNER + i], head_w[d], acc);
        g_v[i] = acc;
    } else if (idx < R3) {
        int p = idx - R2;
        int j = 548 + (p >> 7);
        int k = p & 127;
        int jc = j / TN, n = j - jc * TN;
        g_Wh[(size_t)jc * (TN * TK) + n * 128 + k] = __float2half(0.f);
    } else if (idx < R4) {
        int j = 548 + (idx - R3);
        g_Wcol[j] = 0.f;
        g_biasP[j] = 0.f;
    }
}

// =====================================================================
// xh_kernel: transpose+convert x -> fp16 [b][t][k]; 512 threads
// =====================================================================
__global__ void __launch_bounds__(512)
xh_kernel(const float* __restrict__ x) {
    __shared__ float tile[128][65];
    const int tt0 = blockIdx.x * 64, b = blockIdx.y;
    const float* xb = x + (size_t)b * (NCH * NT);

    #pragma unroll 4
    for (int i = threadIdx.x; i < 128 * 64; i += 512) {
        int c = i >> 6, t = i & 63;
        int gt = tt0 + t;
        tile[c][t] = (gt < NT) ? xb[(size_t)c * NT + gt] : 0.f;
    }
    __syncthreads();
    __half* dst = g_xh + ((size_t)b * 256 + tt0) * 128;
    #pragma unroll 4
    for (int i = threadIdx.x; i < 64 * 64; i += 512) {
        int t = i >> 6, cp = i & 63;
        __half2 h = __floats2half2_rn(tile[2 * cp][t], tile[2 * cp + 1][t]);
        *(__half2*)(dst + (size_t)t * 128 + 2 * cp) = h;
    }
}

// =====================================================================
// gemm_mma: 512 thr, warp 16x72; register epilogue + fp16 staging
//   (unchanged from R16 — measured ~137us)
// =====================================================================
__global__ void __launch_bounds__(512, 2)
gemm_mma(const float* __restrict__ x,
         const float* __restrict__ dt_bias,
         const float* __restrict__ A_log) {
    extern __shared__ __align__(16) unsigned char sm[];
    const uint32_t sbase = smem_u32(sm);
    const int tid = threadIdx.x;
    const int wid = tid >> 5, lane = tid & 31;
    const int gid = lane >> 2, tig = lane & 3;
    const int wm = wid & 7, wn = wid >> 3;
    const int tt = blockIdx.x, jc = blockIdx.y, b = blockIdx.z;
    const int t0 = tt * TM;

    {
        const unsigned char* src = (const unsigned char*)(g_Wh + (size_t)jc * (TN * TK));
        for (int i = tid; i < TN * 16; i += 512) {
            int n = i >> 4, q = i & 15;
            *(uint4*)(sm + SM_BH + n * PITCHB + q * 16) = *(const uint4*)(src + n * 256 + q * 16);
        }
    }
    {
        const uint4* src = (const uint4*)(g_xh + ((size_t)b * 256 + t0) * 128);
        for (int i = tid; i < TM * 16; i += 512) {
            int m = i >> 4, q = i & 15;
            *(uint4*)(sm + SM_AH + m * PITCHB + q * 16) = src[m * 16 + q];
        }
    }
    if (tid < 128) {
        int t = t0 + tid;
        const float* xb = x + (size_t)b * (NCH * NT);
        *(float*)(sm + SM_X128 + tid * 4) = (t < NT) ? xb[(size_t)128 * NT + t] : 0.f;
    }
    if (tid >= 128 && tid < 128 + TN) {
        int i = tid - 128;
        *(float*)(sm + SM_W128 + i * 4) = g_Wcol[jc * TN + i];
        *(float*)(sm + SM_BIAS + i * 4) = g_biasP[jc * TN + i];
    }
    __syncthreads();

    float acc[9][4];
    #pragma unroll
    for (int ni = 0; ni < 9; ni++)
        #pragma unroll
        for (int q = 0; q < 4; q++) acc[ni][q] = 0.f;

    const uint32_t aOff = (uint32_t)(wm * 16 + (lane & 15)) * PITCHB + (uint32_t)(lane >> 4) * 16;
    const uint32_t bBase = (uint32_t)(wn * 72) * PITCHB;
    const uint32_t bOff  = bBase + (uint32_t)(lane & 15) * PITCHB + (uint32_t)(lane >> 4) * 16;
    const uint32_t b2Off = bBase + (uint32_t)(64 + (lane & 7)) * PITCHB + (uint32_t)((lane >> 3) & 1) * 16;

    const uint32_t Ah = sbase + SM_AH + aOff;
    const uint32_t Bb = sbase + SM_BH + bOff;
    const uint32_t Bb2 = sbase + SM_BH + b2Off;

    #pragma unroll
    for (int kk = 0; kk < NKK; kk++) {
        uint32_t ah[4];
        ldsm4(ah, Ah + kk * 32);
        #pragma unroll
        for (int q = 0; q < 4; q++) {
            uint32_t bb[4];
            ldsm4(bb, Bb + (uint32_t)(q * 16) * PITCHB + kk * 32);
            uint32_t f0[2] = { bb[0], bb[2] };
            uint32_t f1[2] = { bb[1], bb[3] };
            mma16816(acc[2 * q],     ah, f0);
            mma16816(acc[2 * q + 1], ah, f1);
        }
        uint32_t b2[2];
        ldsm2(b2, Bb2 + kk * 32);
        mma16816(acc[8], ah, b2);
    }

    __syncthreads();
    {
        __half* hstage = (__half*)sm;
        const float* xs128 = (const float*)(sm + SM_X128);
        const float* sW = (const float*)(sm + SM_W128);
        const float* sBs = (const float*)(sm + SM_BIAS);
        const int r0 = wm * 16 + gid;
        const float xk0 = xs128[r0], xk1 = xs128[r0 + 8];
        #pragma unroll
        for (int ni = 0; ni < 9; ni++) {
            int c = wn * 72 + ni * 8 + 2 * tig;
            int j = jc * TN + c;
            float W0 = sW[c], W1 = sW[c + 1];
            float b0 = sBs[c], b1 = sBs[c + 1];
            float o00 = fmaf(xk0, W0, acc[ni][0] + b0);
            float o01 = fmaf(xk0, W1, acc[ni][1] + b1);
            float o10 = fmaf(xk1, W0, acc[ni][2] + b0);
            float o11 = fmaf(xk1, W1, acc[ni][3] + b1);
            if (j < 256) {
                o00 = __fdividef(o00, 1.f + __expf(-o00));
                o01 = __fdividef(o01, 1.f + __expf(-o01));
                o10 = __fdividef(o10, 1.f + __expf(-o10));
                o11 = __fdividef(o11, 1.f + __expf(-o11));
            }
            if (j < 544) {
                *(__half2*)(hstage + (size_t)r0 * HSP + c) = __floats2half2_rn(o00, o01);
                *(__half2*)(hstage + (size_t)(r0 + 8) * HSP + c) = __floats2half2_rn(o10, o11);
            } else if (j < 548) {
                int h0 = j - 544;
                float vv[2][2] = { { o00, o01 }, { o10, o11 } };
                #pragma unroll
                for (int rr = 0; rr < 2; rr++) {
                    int t = t0 + r0 + rr * 8;
                    if (t < NT) {
                        float* dst = g_dtA + ((size_t)b * NT + t) * 8;
                        #pragma unroll
                        for (int hh = 0; hh < 2; hh++) {
                            int hq = h0 + hh;
                            float rv = vv[rr][hh] + dt_bias[hq];
                            float dt = (rv > 15.f) ? rv : __logf(1.f + __expf(rv));
                            float dA = __expf(dt * -__expf(A_log[hq]));
                            *(float2*)(dst + 2 * hq) = make_float2(dt, dA);
                        }
                    }
                }
            }
        }
    }
    __syncthreads();

    {
        const __half* hstage = (const __half*)sm;
        for (int i = tid; i < TM * 18; i += 512) {
            int row = i / 18, q = i % 18;
            int j = jc * TN + q * 8;
            int t = t0 + row;
            if (t >= NT || j >= 544) continue;
            *(uint4*)(g_zx + ((size_t)b * NT + t) * ROWH + j) =
                *(const uint4*)(hstage + (size_t)row * HSP + q * 8);
        }
    }
}

// =====================================================================
// scan: R12 ring scan + in-loop deferred-rsqrt reduce (replaces gout +
//   combine). Shuffle reductions sit off the recurrence chain.
// =====================================================================
__global__ void __launch_bounds__(160, 4)
scan_kernel(const float* __restrict__ conv_w, const float* __restrict__ conv_b,
            const float* __restrict__ Dp, const float* __restrict__ norm_w,
            const float* __restrict__ head_b, float* __restrict__ out) {
    const int b = blockIdx.x;
    const int tid = threadIdx.x;
    const int lane = tid & 31, wrp = tid >> 5;
    const int c0 = 2 * tid;
    const int h = tid >> 5;

    __shared__ uint32_t sXBC[RD][144];
    __shared__ uint32_t sGZ[RD][128];
    __shared__ float    sDTA[RD][8];
    __shared__ __align__(8) float2 sB2[2][DSTATE];
    __shared__ __align__(8) float2 sC2[2][DSTATE];
    __shared__ __align__(8) float2 sPS[NT][4];
    __shared__ float sfin[5];

    const bool isConv = (tid < 144);
    const bool isScan = (tid < 128);
    const bool isDt   = (tid >= 144 && tid < 148);

    ull wk0 = 0, wk1 = 0, wk2_ = 0, wk3 = 0, cb2 = 0;
    if (isConv) {
        wk0 = pack2(conv_w[c0 * 4 + 0], conv_w[(c0 + 1) * 4 + 0]);
        wk1 = pack2(conv_w[c0 * 4 + 1], conv_w[(c0 + 1) * 4 + 1]);
        wk2_ = pack2(conv_w[c0 * 4 + 2], conv_w[(c0 + 1) * 4 + 2]);
        wk3 = pack2(conv_w[c0 * 4 + 3], conv_w[(c0 + 1) * 4 + 3]);
        cb2 = pack2(conv_b[c0], conv_b[c0 + 1]);
    }
    ull h1 = 0ULL, h2 = 0ULL, h3 = 0ULL;

    ull D2 = 0ULL; float nw0 = 0.f, nw1 = 0.f;
    if (isScan) {
        D2 = dup2(Dp[h]);
        nw0 = norm_w[c0] * g_v[c0];
        nw1 = norm_w[c0 + 1] * g_v[c0 + 1];
    }

    ull s2[DSTATE];
    #pragma unroll
    for (int n = 0; n < DSTATE; n++) s2[n] = 0ULL;

    const __half* zx = g_zx + (size_t)b * NT * ROWH;
    const float* dtp = g_dtA + (size_t)b * NT * 8;

    uint32_t aXBC = isConv ? smem_u32(&sXBC[0][tid]) : 0;
    uint32_t aGZ  = isScan ? smem_u32(&sGZ[0][tid]) : 0;
    uint32_t aDTA = isDt   ? smem_u32(&sDTA[0][2 * (tid - 144)]) : 0;

    #pragma unroll
    for (int d = 0; d < RD - 1; d++) {
        if (isConv) CP_ASYNC4(aXBC + d * 144 * 4, (const void*)(zx + (size_t)d * ROWH + 256 + c0));
        if (isScan) CP_ASYNC4(aGZ + d * 128 * 4, (const void*)(zx + (size_t)d * ROWH + c0));
        if (isDt)   CP_ASYNC8(aDTA + d * 8 * 4, (const void*)(dtp + (size_t)d * 8 + 2 * (tid - 144)));
        CP_COMMIT();
    }

    for (int t = 0; t < NT; t++) {
        const int slot = t & (RD - 1);
        const int buf = t & 1;

        CP_WAIT6();

        float cs0 = 0.f, cs1 = 0.f;
        if (isConv) {
            uint32_t rawu = sXBC[slot][tid];
            float2 fr = __half22float2(*(const __half2*)&rawu);
            ull r2 = pack2(fr.x, fr.y);
            ull cv2 = ffma2(wk3, r2, ffma2(wk2_, h1, ffma2(wk1, h2, ffma2(wk0, h3, cb2))));
            h3 = h2; h2 = h1; h1 = r2;
            float2 cv = unpk2(cv2);
            cs0 = __fdividef(cv.x, 1.f + __expf(-cv.x));
            cs1 = __fdividef(cv.y, 1.f + __expf(-cv.y));
            if (tid >= 128) {
                if (tid < 136) {
                    int k = 2 * (tid - 128);
                    sB2[buf][k]     = make_float2(cs0, cs0);
                    sB2[buf][k + 1] = make_float2(cs1, cs1);
                } else {
                    int k = 2 * (tid - 136);
                    sC2[buf][k]     = make_float2(cs0, cs0);
                    sC2[buf][k + 1] = make_float2(cs1, cs1);
                }
            }
        }
        __syncthreads();

        float g0 = 0.f, g1 = 0.f;
        if (isScan) {
            float2 dtA = *(const float2*)&sDTA[slot][2 * h];
            uint32_t gzu = sGZ[slot][tid];
            float2 gz = __half22float2(*(const __half2*)&gzu);
            ull dA2 = dup2(dtA.y);
            ull dx2 = pack2(dtA.x * cs0, dtA.x * cs1);
            ull ya = fmul2(D2, pack2(cs0, cs1));
            ull yb = 0ULL;
            #pragma unroll
            for (int n = 0; n < DSTATE; n += 2) {
                s2[n]     = ffma2(s2[n],     dA2, fmul2(dx2, *(const ull*)&sB2[buf][n]));
                ya        = ffma2(s2[n],     *(const ull*)&sC2[buf][n], ya);
                s2[n + 1] = ffma2(s2[n + 1], dA2, fmul2(dx2, *(const ull*)&sB2[buf][n + 1]));
                yb        = ffma2(s2[n + 1], *(const ull*)&sC2[buf][n + 1], yb);
            }
            float2 yy = unpk2(ya);
            float2 yz = unpk2(yb);
            g0 = (yy.x + yz.x) * gz.x;
            g1 = (yy.y + yz.y) * gz.y;
        }

        // issue prefetch for step t+7 (before the reduction: off-chain)
        {
            int s = t + RD - 1;
            if (s < NT) {
                int sl = s & (RD - 1);
                if (isConv) CP_ASYNC4(aXBC + sl * 144 * 4, (const void*)(zx + (size_t)s * ROWH + 256 + c0));
                if (isScan) CP_ASYNC4(aGZ + sl * 128 * 4, (const void*)(zx + (size_t)s * ROWH + c0));
                if (isDt)   CP_ASYNC8(aDTA + sl * 8 * 4, (const void*)(dtp + (size_t)s * 8 + 2 * (tid - 144)));
            }
            CP_COMMIT();
        }

        // deferred-rsqrt partials (independent of next step's recurrence)
        if (isScan) {
            float ss = fmaf(g0, g0, g1 * g1);
            float p  = fmaf(g0, nw0, g1 * nw1);
            #pragma unroll
            for (int o = 16; o > 0; o >>= 1) {
                ss += __shfl_xor_sync(0xffffffffu, ss, o);
                p  += __shfl_xor_sync(0xffffffffu, p, o);
            }
            if (lane == 0) sPS[t][wrp] = make_float2(ss, p);
        }
    }

    // final phase: rsqrt + pool + head
    __syncthreads();
    float facc = 0.f;
    for (int t = tid; t < NT; t += 160) {
        float2 a = sPS[t][0], b2 = sPS[t][1], c = sPS[t][2], d = sPS[t][3];
        float SS = (a.x + b2.x) + (c.x + d.x);
        float P  = (a.y + b2.y) + (c.y + d.y);
        facc = fmaf(P, rsqrtf(SS * (1.f / 256.f) + EPSV), facc);
    }
    #pragma unroll
    for (int o = 16; o > 0; o >>= 1) facc += __shfl_xor_sync(0xffffffffu, facc, o);
    if (lane == 0) sfin[wrp] = facc;
    __syncthreads();
    if (tid == 0) {
        float tot = (sfin[0] + sfin[1]) + (sfin[2] + sfin[3]) + sfin[4];
        out[b] = tot * (1.f / (float)NT) + head_b[0];
    }
}

// =====================================================================
// launch
// =====================================================================
extern "C" void kernel_launch(void* const* d_in, const int* in_sizes, int n_in,
                              void* d_out, int out_size) {
    const float* x          = (const float*)d_in[0];
    const float* mixer_w    = (const float*)d_in[1];
    const float* mixer_b    = (const float*)d_in[2];
    const float* in_proj_w  = (const float*)d_in[3];
    const float* conv_w     = (const float*)d_in[4];
    const float* conv_b     = (const float*)d_in[5];
    const float* dt_bias    = (const float*)d_in[6];
    const float* A_log      = (const float*)d_in[7];
    const float* Dvec       = (const float*)d_in[8];
    const float* norm_w     = (const float*)d_in[9];
    const float* out_proj_w = (const float*)d_in[10];
    const float* head_w     = (const float*)d_in[11];
    const float* head_b     = (const float*)d_in[12];
    float* out = (float*)d_out;

    const int NW = DPROJ * NCH;
    prep1a_kernel<<<(4 * NW + 255) / 256, 256>>>(in_proj_w, mixer_w);
    {
        int total = NW + DPROJ + DINNER + 28 * 128 + 28;
        prep1b_kernel<<<(total + 255) / 256, 256>>>(in_proj_w, mixer_b,
                                                    out_proj_w, head_w);
    }
    {
        dim3 grid(4, BSZ);
        xh_kernel<<<grid, 512>>>(x);
    }
    {
        cudaFuncSetAttribute(gemm_mma,
                             cudaFuncAttributeMaxDynamicSharedMemorySize, SMEM_SZ);
        dim3 grid(2, NJC, BSZ);
        gemm_mma<<<grid, 512, SMEM_SZ>>>(x, dt_bias, A_log);
    }
    scan_kernel<<<BSZ, 160>>>(conv_w, conv_b, Dvec, norm_w, head_b, out);
}